// round 10
// baseline (speedup 1.0000x reference)
#include <cuda_runtime.h>
#include <math.h>
#include <stdint.h>

#define QLEN 1024
#define MLEN 1024
#define BSZ 4
#define DMODEL 512
#define NH 8
#define DHEAD 64
#define DFF 2048
#define NLAYER 3
#define KLEN (QLEN + MLEN)
#define MROWS (QLEN * BSZ)   /* 4096 */
#define CROWS (KLEN * BSZ)   /* 8192 */

// ---------------- scratch (device globals; no allocation allowed) -------------
static __device__ float g_h[MROWS * DMODEL];
static __device__ float g_c[CROWS * DMODEL];
static __device__ float g_q[MROWS * DMODEL];
static __device__ float g_kv[CROWS * 2 * DMODEL];
static __device__ float g_vec[MROWS * DMODEL];
static __device__ float g_ff[MROWS * DFF];
static __device__ float g_tmp[MROWS * DMODEL];

// ---------------- helpers ------------------------------------------------------
__device__ __forceinline__ uint32_t f2tf(float x) {
    uint32_t r;
    asm("cvt.rna.tf32.f32 %0, %1;" : "=r"(r) : "f"(x));
    return r;
}
__device__ __forceinline__ float4 tf4(float4 v) {
    return make_float4(__uint_as_float(f2tf(v.x)), __uint_as_float(f2tf(v.y)),
                       __uint_as_float(f2tf(v.z)), __uint_as_float(f2tf(v.w)));
}

__device__ __forceinline__ void mma_tf32(float* c, const uint32_t* a, const uint32_t* b) {
    asm volatile(
        "mma.sync.aligned.m16n8k8.row.col.f32.tf32.tf32.f32 "
        "{%0,%1,%2,%3}, {%4,%5,%6,%7}, {%8,%9}, {%0,%1,%2,%3};"
        : "+f"(c[0]), "+f"(c[1]), "+f"(c[2]), "+f"(c[3])
        : "r"(a[0]), "r"(a[1]), "r"(a[2]), "r"(a[3]), "r"(b[0]), "r"(b[1]));
}

__device__ __forceinline__ void cp16(void* smem, const void* gmem) {
    uint32_t s = (uint32_t)__cvta_generic_to_shared(smem);
    asm volatile("cp.async.ca.shared.global [%0], [%1], 16;\n" :: "r"(s), "l"(gmem));
}
#define CP_COMMIT() asm volatile("cp.async.commit_group;\n" ::: "memory")
#define CP_WAIT1()  asm volatile("cp.async.wait_group 1;\n" ::: "memory")
#define CP_WAIT0()  asm volatile("cp.async.wait_group 0;\n" ::: "memory")

// ---------------- embedding + sinusoidal position -----------------------------
__global__ void embed_kernel(const int* __restrict__ inp,
                             const float* __restrict__ emb,
                             float* __restrict__ h) {
    int idx = blockIdx.x * blockDim.x + threadIdx.x;
    if (idx >= MROWS * DMODEL) return;
    int d   = idx & (DMODEL - 1);
    int row = idx >> 9;
    int i   = row >> 2;
    int tok = inp[row];
    float val = emb[(size_t)tok * DMODEL + d] * 22.62741699796952f;
    float pos = (float)(QLEN - 1 - i);
    int j = (d < DMODEL / 2) ? d : d - DMODEL / 2;
    float f = powf(10000.0f, -(float)j * (1.0f / 256.0f));
    float ang = pos * f;
    val += (d < DMODEL / 2) ? sinf(ang) : cosf(ang);
    h[idx] = val;
}

// ---------------- concat ------------------------------------------------------
__global__ void concat_kernel(const float* __restrict__ mems_l,
                              const float* __restrict__ h,
                              float* __restrict__ c) {
    const int nhalf = MROWS * DMODEL / 4;
    int idx = blockIdx.x * blockDim.x + threadIdx.x;
    if (idx >= 2 * nhalf) return;
    float4 v = (idx < nhalf) ? ((const float4*)mems_l)[idx]
                             : ((const float4*)h)[idx - nhalf];
    ((float4*)c)[idx] = v;
}

// ---------------- TF32 GEMM: 128x64 tile, 128 threads, 3-stage ring -----------
// 4 warps, warp-tile 32x64. 4 CTAs/SM (regs<=128, smem 43.5KB).
// EPI: 0 = none, 1 = relu(x + bias), 2 = x + res, 3 = x + bias + res
#define GN_ASZ  (128 * 20)          /* 2560 floats */
#define GN_BSZ  (16 * 72)           /* 1152 floats */
#define GN_STG  (GN_ASZ + GN_BSZ)   /* 3712 floats */
#define GN_SMEM (3 * GN_STG * 4)    /* 44544 bytes (< 48KB default) */

template <int EPI>
__global__ __launch_bounds__(128, 4)
void gemm_tf32_kernel(const float* __restrict__ A, const float* __restrict__ B,
                      float* __restrict__ C, int M, int N, int K,
                      const float* __restrict__ bias, const float* __restrict__ res) {
    extern __shared__ __align__(16) float sm[];

    const int t    = threadIdx.x;
    const int lane = t & 31;
    const int warp = t >> 5;           // 0..3
    const int lr   = lane >> 2;
    const int lc   = lane & 3;
    const int bm   = blockIdx.y * 128, bn = blockIdx.x * 64;
    const int m0   = warp * 32;

    // cp.async mappings
    const int bkB = t >> 4;            // 0..7
    const int bnB = (t & 15) * 4;      // 0..60

    const float* Aptr = A + (size_t)(bm + t) * K;
    const float* Bptr = B + (size_t)bkB * N + bn + bnB;
    const size_t Bstep8 = (size_t)8 * N;

    const int aOff  = t * 20;
    const int bOff0 = GN_ASZ + bkB * 72 + bnB;
    const int bOff1 = GN_ASZ + (bkB + 8) * 72 + bnB;

    float acc[2][8][4];
#pragma unroll
    for (int i = 0; i < 2; i++)
#pragma unroll
        for (int j = 0; j < 8; j++)
#pragma unroll
            for (int r = 0; r < 4; r++) acc[i][j][r] = 0.0f;

    const int KB = K >> 4;

    // prologue: stages 0 and 1
#pragma unroll
    for (int s = 0; s < 2; s++) {
        float* st = sm + s * GN_STG;
        const float* Ap = Aptr + s * 16;
        const float* Bp = Bptr + (size_t)s * 16 * N;
#pragma unroll
        for (int c = 0; c < 4; c++) cp16(st + aOff + c * 4, Ap + c * 4);
        cp16(st + bOff0, Bp);
        cp16(st + bOff1, Bp + Bstep8);
        CP_COMMIT();
    }

    int rbuf = 0, wbuf = 2;
    for (int kb = 0; kb < KB; kb++) {
        if (kb + 1 < KB) CP_WAIT1(); else CP_WAIT0();
        __syncthreads();

        if (kb + 2 < KB) {
            float* st = sm + wbuf * GN_STG;
            const float* Ap = Aptr + (kb + 2) * 16;
            const float* Bp = Bptr + (size_t)(kb + 2) * 16 * N;
#pragma unroll
            for (int c = 0; c < 4; c++) cp16(st + aOff + c * 4, Ap + c * 4);
            cp16(st + bOff0, Bp);
            cp16(st + bOff1, Bp + Bstep8);
            CP_COMMIT();
        }

        const float* As_ = sm + rbuf * GN_STG;
        const float* Bs_ = As_ + GN_ASZ;

        uint32_t af[2][2][4];
        uint32_t bf[2][8][2];
#pragma unroll
        for (int ks = 0; ks < 2; ks++) {
            const int k0 = ks * 8;
#pragma unroll
            for (int mt = 0; mt < 2; mt++) {
                int mr = m0 + mt * 16 + lr;
                af[ks][mt][0] = __float_as_uint(As_[mr * 20 + k0 + lc]);
                af[ks][mt][1] = __float_as_uint(As_[(mr + 8) * 20 + k0 + lc]);
                af[ks][mt][2] = __float_as_uint(As_[mr * 20 + k0 + lc + 4]);
                af[ks][mt][3] = __float_as_uint(As_[(mr + 8) * 20 + k0 + lc + 4]);
            }
#pragma unroll
            for (int nt = 0; nt < 8; nt++) {
                int nc = nt * 8 + lr;
                bf[ks][nt][0] = __float_as_uint(Bs_[(k0 + lc) * 72 + nc]);
                bf[ks][nt][1] = __float_as_uint(Bs_[(k0 + lc + 4) * 72 + nc]);
            }
        }
#pragma unroll
        for (int ks = 0; ks < 2; ks++)
#pragma unroll
            for (int nt = 0; nt < 8; nt++) {
                mma_tf32(acc[0][nt], af[ks][0], bf[ks][nt]);
                mma_tf32(acc[1][nt], af[ks][1], bf[ks][nt]);
            }

        rbuf = (rbuf + 1) % 3;
        wbuf = (wbuf + 1) % 3;
    }

#pragma unroll
    for (int mt = 0; mt < 2; mt++) {
#pragma unroll
        for (int half = 0; half < 2; half++) {
            int row = bm + m0 + mt * 16 + lr + half * 8;
            float* Crow = C + (size_t)row * N + bn;
            const float* Rrow = (EPI >= 2) ? (res + (size_t)row * N + bn) : nullptr;
#pragma unroll
            for (int nt = 0; nt < 8; nt++) {
                int col = nt * 8 + lc * 2;
                float2 v = make_float2(acc[mt][nt][half * 2], acc[mt][nt][half * 2 + 1]);
                if (EPI == 1 || EPI == 3) {
                    float2 bb = *(const float2*)(bias + bn + col);
                    v.x += bb.x; v.y += bb.y;
                }
                if (EPI == 1) { v.x = fmaxf(v.x, 0.f); v.y = fmaxf(v.y, 0.f); }
                if (EPI >= 2) {
                    float2 rr = *(const float2*)(Rrow + col);
                    v.x += rr.x; v.y += rr.y;
                }
                *(float2*)&Crow[col] = v;
            }
        }
    }
}

// ---------------- tensor-core flash attention, 64q x 64k, double-buffered KV --
// grid: (QLEN/64, BSZ, NH), 256 threads (8 warps). 3 barriers per tile.
#define AT_KS 68
#define AT_VS 72
#define AT_SS 68
#define AT_QS 68                                 /* Q overlay stride: mult of 4 -> float4 OK */
#define AT_KS_OFF 0                              /* Ks[2][64*68] */
#define AT_VS_OFF (2 * 64 * AT_KS)               /* Vs[2][64*72] */
#define AT_SS_OFF (AT_VS_OFF + 2 * 64 * AT_VS)   /* Ss[64*68]    */
#define AT_ML_OFF (AT_SS_OFF + 64 * AT_SS)
#define AT_SMEM ((AT_ML_OFF + 192) * 4)          /* 89856 bytes */

__global__ __launch_bounds__(256)
void attn_tc_kernel(const float* __restrict__ Q, const float* __restrict__ KV,
                    float* __restrict__ Vout) {
    extern __shared__ __align__(16) float smf[];
    float* KsB[2] = { smf + AT_KS_OFF, smf + AT_KS_OFF + 64 * AT_KS };
    float* VsB[2] = { smf + AT_VS_OFF, smf + AT_VS_OFF + 64 * AT_VS };
    float* Ss  = smf + AT_SS_OFF;
    float* m_s = smf + AT_ML_OFF;
    float* l_s = m_s + 64;
    float* al_s = m_s + 128;

    const int qb = blockIdx.x, b = blockIdx.y, hh = blockIdx.z;
    const int t = threadIdx.x, lane = t & 31, warp = t >> 5;
    const int lr = lane >> 2, lc = lane & 3;

    const int kb2 = (warp & 1) * 32;     // QK: kj half
    const int nq0 = (warp >> 1) * 16;    // QK: q columns
    const int mq0 = (warp & 3) * 16;     // PV: q rows
    const int nd0 = (warp >> 2) * 32;    // PV: d cols
    const int kjA = t >> 4;              // KV staging rows kjA + 16s
    const int d4A = (t & 15) * 4;

    const int nTiles = 17 + qb;
    const int lastTile = nTiles - 1;

    // ---- prologue: Q (tf32) into Ss overlay (stride 68, 16B-aligned rows)
    float* Qs = Ss;
    for (int idx = t; idx < 64 * 16; idx += 256) {
        int qi = idx >> 4, d4 = (idx & 15) * 4;
        float4 v = *(const float4*)&Q[((size_t)((qb * 64 + qi) * BSZ + b)) * DMODEL
                                      + hh * DHEAD + d4];
        *(float4*)&Qs[qi * AT_QS + d4] = tf4(v);
    }
    float4 kr[4], vr[4];
#pragma unroll
    for (int s = 0; s < 4; s++) {
        size_t ba = ((size_t)(kjA + 16 * s) * BSZ + b) * (2 * DMODEL) + hh * DHEAD + d4A;
        kr[s] = *(const float4*)&KV[ba];
        vr[s] = *(const float4*)&KV[ba + DMODEL];
    }
#pragma unroll
    for (int s = 0; s < 4; s++) {
        *(float4*)&KsB[0][(kjA + 16 * s) * AT_KS + d4A] = tf4(kr[s]);
        *(float4*)&VsB[0][(kjA + 16 * s) * AT_VS + d4A] = tf4(vr[s]);
    }
    if (t < 64) { m_s[t] = -INFINITY; l_s[t] = 0.0f; }
    __syncthreads();

    // persistent Q fragments
    uint32_t qf[2][8][2];
#pragma unroll
    for (int nt = 0; nt < 2; nt++)
#pragma unroll
        for (int c = 0; c < 8; c++) {
            int qcol = nq0 + nt * 8 + lr;
            qf[nt][c][0] = __float_as_uint(Qs[qcol * AT_QS + c * 8 + lc]);
            qf[nt][c][1] = __float_as_uint(Qs[qcol * AT_QS + c * 8 + lc + 4]);
        }
    __syncthreads();   // all qf reads done before Ss is reused for scores

    float oacc[4][4];
#pragma unroll
    for (int i = 0; i < 4; i++)
#pragma unroll
        for (int j = 0; j < 4; j++) oacc[i][j] = 0.0f;

    int buf = 0;
    for (int tile = 0; tile < nTiles; tile++) {
        const int j0 = tile * 64;
        const float* Ks = KsB[buf];
        const float* Vs = VsB[buf];

        // prefetch next KV tile into registers (covered by QK + softmax)
        if (tile + 1 < nTiles) {
#pragma unroll
            for (int s = 0; s < 4; s++) {
                size_t ba = ((size_t)(j0 + 64 + kjA + 16 * s) * BSZ + b) * (2 * DMODEL)
                            + hh * DHEAD + d4A;
                kr[s] = *(const float4*)&KV[ba];
                vr[s] = *(const float4*)&KV[ba + DMODEL];
            }
        }

        // S^T = K @ Q^T
        float sacc[2][2][4];
#pragma unroll
        for (int i = 0; i < 2; i++)
#pragma unroll
            for (int j = 0; j < 2; j++)
#pragma unroll
                for (int r = 0; r < 4; r++) sacc[i][j][r] = 0.0f;
#pragma unroll
        for (int mt2 = 0; mt2 < 2; mt2++) {
#pragma unroll
            for (int c = 0; c < 8; c++) {
                uint32_t af[4];
                int kr0 = (kb2 + mt2 * 16 + lr) * AT_KS;
                af[0] = __float_as_uint(Ks[kr0 + c * 8 + lc]);
                af[1] = __float_as_uint(Ks[kr0 + 8 * AT_KS + c * 8 + lc]);
                af[2] = __float_as_uint(Ks[kr0 + c * 8 + lc + 4]);
                af[3] = __float_as_uint(Ks[kr0 + 8 * AT_KS + c * 8 + lc + 4]);
                mma_tf32(sacc[mt2][0], af, qf[0][c]);
                mma_tf32(sacc[mt2][1], af, qf[1][c]);
            }
        }
        const bool maskTile = (tile == lastTile);
#pragma unroll
        for (int mt2 = 0; mt2 < 2; mt2++)
#pragma unroll
            for (int nt = 0; nt < 2; nt++)
#pragma unroll
                for (int i = 0; i < 4; i++) {
                    int kjl = kb2 + mt2 * 16 + lr + ((i >> 1) ? 8 : 0);
                    int ql  = nq0 + nt * 8 + 2 * lc + (i & 1);
                    float v = sacc[mt2][nt][i] * 0.125f;
                    if (maskTile && (j0 + kjl > MLEN + qb * 64 + ql)) v = -INFINITY;
                    Ss[ql * AT_SS + kjl] = v;
                }
        __syncthreads();   // (1) scores visible to softmax

        // online softmax over 64 keys
        {
            int srow = t >> 2, sq = t & 3;
            float sv[16];
            float mx = -INFINITY;
#pragma unroll
            for (int j = 0; j < 16; j++) {
                sv[j] = Ss[srow * AT_SS + 4 * j + sq];
                mx = fmaxf(mx, sv[j]);
            }
            mx = fmaxf(mx, __shfl_xor_sync(0xffffffffu, mx, 1));
            mx = fmaxf(mx, __shfl_xor_sync(0xffffffffu, mx, 2));
            float mOld = m_s[srow];
            float mNew = fmaxf(mOld, mx);
            float al   = expf(mOld - mNew);
            float sum = 0.0f;
#pragma unroll
            for (int j = 0; j < 16; j++) {
                float p = expf(sv[j] - mNew);
                Ss[srow * AT_SS + 4 * j + sq] = __uint_as_float(f2tf(p));
                sum += p;
            }
            sum += __shfl_xor_sync(0xffffffffu, sum, 1);
            sum += __shfl_xor_sync(0xffffffffu, sum, 2);
            if (sq == 0) { m_s[srow] = mNew; l_s[srow] = l_s[srow] * al + sum; al_s[srow] = al; }
        }
        __syncthreads();   // (2) probs + al visible to PV

        // stage next KV tile into the other buffer (overlaps with PV)
        if (tile + 1 < nTiles) {
#pragma unroll
            for (int s = 0; s < 4; s++) {
                *(float4*)&KsB[buf ^ 1][(kjA + 16 * s) * AT_KS + d4A] = tf4(kr[s]);
                *(float4*)&VsB[buf ^ 1][(kjA + 16 * s) * AT_VS + d4A] = tf4(vr[s]);
            }
        }

        // O += P @ V
        float a0 = al_s[mq0 + lr], a1 = al_s[mq0 + 8 + lr];
#pragma unroll
        for (int nt = 0; nt < 4; nt++) {
            oacc[nt][0] *= a0; oacc[nt][1] *= a0;
            oacc[nt][2] *= a1; oacc[nt][3] *= a1;
        }
#pragma unroll
        for (int c = 0; c < 8; c++) {
            uint32_t af[4];
            int pr0 = (mq0 + lr) * AT_SS;
            af[0] = __float_as_uint(Ss[pr0 + c * 8 + lc]);
            af[1] = __float_as_uint(Ss[pr0 + 8 * AT_SS + c * 8 + lc]);
            af[2] = __float_as_uint(Ss[pr0 + c * 8 + lc + 4]);
            af[3] = __float_as_uint(Ss[pr0 + 8 * AT_SS + c * 8 + lc + 4]);
#pragma unroll
            for (int nt = 0; nt < 4; nt++) {
                uint32_t bfv[2];
                bfv[0] = __float_as_uint(Vs[(c * 8 + lc) * AT_VS + nd0 + nt * 8 + lr]);
                bfv[1] = __float_as_uint(Vs[(c * 8 + lc + 4) * AT_VS + nd0 + nt * 8 + lr]);
                mma_tf32(oacc[nt], af, bfv);
            }
        }
        __syncthreads();   // (3) PV done (Ss free) + staged KV visible
        buf ^= 1;
    }

    // final normalize + store
#pragma unroll
    for (int half = 0; half < 2; half++) {
        int q = mq0 + lr + half * 8;
        float invl = 1.0f / l_s[q];
        float* orow = &Vout[((size_t)((qb * 64 + q) * BSZ + b)) * DMODEL + hh * DHEAD];
#pragma unroll
        for (int nt = 0; nt < 4; nt++) {
            float2 v = make_float2(oacc[nt][half * 2] * invl, oacc[nt][half * 2 + 1] * invl);
            *(float2*)&orow[nd0 + nt * 8 + 2 * lc] = v;
        }
    }
}

// ---------------- layernorm ---------------------------------------------------
__global__ __launch_bounds__(128)
void ln_kernel(const float* __restrict__ x, const float* __restrict__ g,
               const float* __restrict__ bparm, float* __restrict__ out) {
    const int row = blockIdx.x;
    const int t = threadIdx.x;
    float4 v = ((const float4*)(x + (size_t)row * DMODEL))[t];
    float s  = v.x + v.y + v.z + v.w;
    float s2 = fmaf(v.x, v.x, fmaf(v.y, v.y, fmaf(v.z, v.z, v.w * v.w)));
#pragma unroll
    for (int o = 16; o > 0; o >>= 1) {
        s  += __shfl_down_sync(0xffffffffu, s, o);
        s2 += __shfl_down_sync(0xffffffffu, s2, o);
    }
    __shared__ float ss[4], ss2[4];
    int w = t >> 5;
    if ((t & 31) == 0) { ss[w] = s; ss2[w] = s2; }
    __syncthreads();
    float tot  = ss[0] + ss[1] + ss[2] + ss[3];
    float tot2 = ss2[0] + ss2[1] + ss2[2] + ss2[3];
    float mu  = tot * (1.0f / DMODEL);
    float var = tot2 * (1.0f / DMODEL) - mu * mu;
    float rs  = rsqrtf(var + 1e-5f);
    float4 gg = ((const float4*)g)[t];
    float4 bb = ((const float4*)bparm)[t];
    float4 o;
    o.x = (v.x - mu) * rs * gg.x + bb.x;
    o.y = (v.y - mu) * rs * gg.y + bb.y;
    o.z = (v.z - mu) * rs * gg.z + bb.z;
    o.w = (v.w - mu) * rs * gg.w + bb.w;
    ((float4*)(out + (size_t)row * DMODEL))[t] = o;
}

// ---------------- launch ------------------------------------------------------
extern "C" void kernel_launch(void* const* d_in, const int* in_sizes, int n_in,
                              void* d_out, int out_size) {
    const int*   inp  = (const int*)d_in[0];
    const float* emb  = (const float*)d_in[1];
    const float* mems = (const float*)d_in[2];
    const float* Wq   = (const float*)d_in[3];
    const float* Wkv  = (const float*)d_in[4];
    const float* Wo   = (const float*)d_in[5];
    const float* ln1g = (const float*)d_in[6];
    const float* ln1b = (const float*)d_in[7];
    const float* W1   = (const float*)d_in[8];
    const float* b1   = (const float*)d_in[9];
    const float* W2   = (const float*)d_in[10];
    const float* b2   = (const float*)d_in[11];
    const float* ln2g = (const float*)d_in[12];
    const float* ln2b = (const float*)d_in[13];
    float* out = (float*)d_out;

    float *h, *c, *q, *kv, *vec, *ff, *tmp;
    cudaGetSymbolAddress((void**)&h,   g_h);
    cudaGetSymbolAddress((void**)&c,   g_c);
    cudaGetSymbolAddress((void**)&q,   g_q);
    cudaGetSymbolAddress((void**)&kv,  g_kv);
    cudaGetSymbolAddress((void**)&vec, g_vec);
    cudaGetSymbolAddress((void**)&ff,  g_ff);
    cudaGetSymbolAddress((void**)&tmp, g_tmp);

    cudaFuncSetAttribute(attn_tc_kernel, cudaFuncAttributeMaxDynamicSharedMemorySize, AT_SMEM);

    embed_kernel<<<(MROWS * DMODEL + 255) / 256, 256>>>(inp, emb, h);

    for (int l = 0; l < NLAYER; l++) {
        concat_kernel<<<(CROWS * DMODEL / 4 + 255) / 256, 256>>>(
            mems + (size_t)l * MLEN * BSZ * DMODEL, h, c);

        gemm_tf32_kernel<0><<<dim3(DMODEL / 64, MROWS / 128), 128, GN_SMEM>>>(
            h, Wq + (size_t)l * DMODEL * DMODEL, q,
            MROWS, DMODEL, DMODEL, nullptr, nullptr);

        gemm_tf32_kernel<0><<<dim3(2 * DMODEL / 64, CROWS / 128), 128, GN_SMEM>>>(
            c, Wkv + (size_t)l * DMODEL * 2 * DMODEL, kv,
            CROWS, 2 * DMODEL, DMODEL, nullptr, nullptr);

        attn_tc_kernel<<<dim3(QLEN / 64, BSZ, NH), 256, AT_SMEM>>>(q, kv, vec);

        gemm_tf32_kernel<2><<<dim3(DMODEL / 64, MROWS / 128), 128, GN_SMEM>>>(
            vec, Wo + (size_t)l * DMODEL * DMODEL, tmp,
            MROWS, DMODEL, DMODEL, nullptr, h);

        ln_kernel<<<MROWS, 128>>>(tmp, ln1g + l * DMODEL, ln1b + l * DMODEL, h);

        gemm_tf32_kernel<1><<<dim3(DFF / 64, MROWS / 128), 128, GN_SMEM>>>(
            h, W1 + (size_t)l * DMODEL * DFF, ff,
            MROWS, DFF, DMODEL, b1 + l * DFF, nullptr);

        gemm_tf32_kernel<3><<<dim3(DMODEL / 64, MROWS / 128), 128, GN_SMEM>>>(
            ff, W2 + (size_t)l * DFF * DMODEL, tmp,
            MROWS, DMODEL, DFF, b2 + l * DMODEL, h);

        ln_kernel<<<MROWS, 128>>>(tmp, ln2g + l * DMODEL, ln2b + l * DMODEL,
                                  (l == NLAYER - 1) ? out : h);
    }
}

// round 12
// speedup vs baseline: 1.4028x; 1.4028x over previous
#include <cuda_runtime.h>
#include <math.h>
#include <stdint.h>

#define QLEN 1024
#define MLEN 1024
#define BSZ 4
#define DMODEL 512
#define NH 8
#define DHEAD 64
#define DFF 2048
#define NLAYER 3
#define KLEN (QLEN + MLEN)
#define MROWS (QLEN * BSZ)   /* 4096 */
#define CROWS (KLEN * BSZ)   /* 8192 */

// ---------------- scratch (device globals; no allocation allowed) -------------
static __device__ float g_h[MROWS * DMODEL];
static __device__ float g_c[CROWS * DMODEL];
static __device__ float g_q[MROWS * DMODEL];
static __device__ float g_kv[CROWS * 2 * DMODEL];
static __device__ float g_vec[MROWS * DMODEL];
static __device__ float g_ff[MROWS * DFF];
static __device__ float g_tmp[MROWS * DMODEL];

// ---------------- helpers ------------------------------------------------------
__device__ __forceinline__ uint32_t f2tf(float x) {
    uint32_t r;
    asm("cvt.rna.tf32.f32 %0, %1;" : "=r"(r) : "f"(x));
    return r;
}
__device__ __forceinline__ float4 tf4(float4 v) {
    return make_float4(__uint_as_float(f2tf(v.x)), __uint_as_float(f2tf(v.y)),
                       __uint_as_float(f2tf(v.z)), __uint_as_float(f2tf(v.w)));
}

__device__ __forceinline__ void mma_tf32(float* c, const uint32_t* a, const uint32_t* b) {
    asm volatile(
        "mma.sync.aligned.m16n8k8.row.col.f32.tf32.tf32.f32 "
        "{%0,%1,%2,%3}, {%4,%5,%6,%7}, {%8,%9}, {%0,%1,%2,%3};"
        : "+f"(c[0]), "+f"(c[1]), "+f"(c[2]), "+f"(c[3])
        : "r"(a[0]), "r"(a[1]), "r"(a[2]), "r"(a[3]), "r"(b[0]), "r"(b[1]));
}

__device__ __forceinline__ void cp16(void* smem, const void* gmem) {
    uint32_t s = (uint32_t)__cvta_generic_to_shared(smem);
    asm volatile("cp.async.ca.shared.global [%0], [%1], 16;\n" :: "r"(s), "l"(gmem));
}
#define CP_COMMIT() asm volatile("cp.async.commit_group;\n" ::: "memory")
#define CP_WAIT1()  asm volatile("cp.async.wait_group 1;\n" ::: "memory")
#define CP_WAIT0()  asm volatile("cp.async.wait_group 0;\n" ::: "memory")

// ---------------- embedding + sinusoidal position -----------------------------
__global__ void embed_kernel(const int* __restrict__ inp,
                             const float* __restrict__ emb,
                             float* __restrict__ h) {
    int idx = blockIdx.x * blockDim.x + threadIdx.x;
    if (idx >= MROWS * DMODEL) return;
    int d   = idx & (DMODEL - 1);
    int row = idx >> 9;
    int i   = row >> 2;
    int tok = inp[row];
    float val = emb[(size_t)tok * DMODEL + d] * 22.62741699796952f;
    float pos = (float)(QLEN - 1 - i);
    int j = (d < DMODEL / 2) ? d : d - DMODEL / 2;
    float f = powf(10000.0f, -(float)j * (1.0f / 256.0f));
    float ang = pos * f;
    val += (d < DMODEL / 2) ? sinf(ang) : cosf(ang);
    h[idx] = val;
}

// ---------------- concat ------------------------------------------------------
__global__ void concat_kernel(const float* __restrict__ mems_l,
                              const float* __restrict__ h,
                              float* __restrict__ c) {
    const int nhalf = MROWS * DMODEL / 4;
    int idx = blockIdx.x * blockDim.x + threadIdx.x;
    if (idx >= 2 * nhalf) return;
    float4 v = (idx < nhalf) ? ((const float4*)mems_l)[idx]
                             : ((const float4*)h)[idx - nhalf];
    ((float4*)c)[idx] = v;
}

// ---------------- TF32 GEMM: 128x128x32, 256 threads, 3-stage ring ------------
// EPI: 0 = none, 1 = relu(x + bias), 2 = x + res, 3 = x + bias + res
// Stage: A[128][36] (k-major stride 36, conflict-free), B[32][136].
#define G2_ASZ  (128 * 36)          /* 4608 floats */
#define G2_BSZ  (32 * 136)          /* 4352 floats */
#define G2_STG  (G2_ASZ + G2_BSZ)   /* 8960 floats */
#define G2_SMEM (3 * G2_STG * 4)    /* 107520 bytes */

template <int EPI>
__global__ __launch_bounds__(256, 2)
void gemm_tf32_kernel(const float* __restrict__ A, const float* __restrict__ B,
                      float* __restrict__ C, int M, int N, int K,
                      const float* __restrict__ bias, const float* __restrict__ res) {
    extern __shared__ __align__(16) float sm[];

    const int t    = threadIdx.x;
    const int lane = t & 31;
    const int warp = t >> 5;
    const int wm   = warp & 3;
    const int wn   = warp >> 2;
    const int lr   = lane >> 2;
    const int lc   = lane & 3;
    const int bm   = blockIdx.y * 128, bn = blockIdx.x * 128;
    const int m0   = wm * 32, n0 = wn * 64;

    // cp.async mappings (per stage: A 4 x cp16, B 4 x cp16 per thread)
    const int amA = t >> 1;            // A row 0..127
    const int akA = (t & 1) * 16;      // A k half: 0 or 16
    const int bkB = t >> 5;            // B k row 0..7 (+8,+16,+24)
    const int bnB = (t & 31) * 4;      // B col 0..124

    const float* Aptr = A + (size_t)(bm + amA) * K + akA;
    const float* Bptr = B + (size_t)bkB * N + bn + bnB;
    const size_t Bstep8 = (size_t)8 * N;

    const int aOff  = amA * 36 + akA;
    const int bOff  = G2_ASZ + bkB * 136 + bnB;

    float acc[2][8][4];
#pragma unroll
    for (int i = 0; i < 2; i++)
#pragma unroll
        for (int j = 0; j < 8; j++)
#pragma unroll
            for (int r = 0; r < 4; r++) acc[i][j][r] = 0.0f;

    const int KB = K >> 5;

    // prologue: stages 0 and 1
#pragma unroll
    for (int s = 0; s < 2; s++) {
        float* st = sm + s * G2_STG;
        const float* Ap = Aptr + s * 32;
        const float* Bp = Bptr + (size_t)s * 32 * N;
#pragma unroll
        for (int c = 0; c < 4; c++) cp16(st + aOff + c * 4, Ap + c * 4);
#pragma unroll
        for (int r = 0; r < 4; r++) cp16(st + bOff + r * 8 * 136, Bp + r * Bstep8);
        CP_COMMIT();
    }

    int rbuf = 0, wbuf = 2;
    for (int kb = 0; kb < KB; kb++) {
        if (kb + 1 < KB) CP_WAIT1(); else CP_WAIT0();
        __syncthreads();

        // issue next stage before compute
        if (kb + 2 < KB) {
            float* st = sm + wbuf * G2_STG;
            const float* Ap = Aptr + (kb + 2) * 32;
            const float* Bp = Bptr + (size_t)(kb + 2) * 32 * N;
#pragma unroll
            for (int c = 0; c < 4; c++) cp16(st + aOff + c * 4, Ap + c * 4);
#pragma unroll
            for (int r = 0; r < 4; r++) cp16(st + bOff + r * 8 * 136, Bp + r * Bstep8);
            CP_COMMIT();
        }

        const float* As_ = sm + rbuf * G2_STG;
        const float* Bs_ = As_ + G2_ASZ;

#pragma unroll
        for (int ks = 0; ks < 4; ks++) {
            const int k0 = ks * 8;
            uint32_t af[2][4];
#pragma unroll
            for (int mt = 0; mt < 2; mt++) {
                int mr = m0 + mt * 16 + lr;
                af[mt][0] = __float_as_uint(As_[mr * 36 + k0 + lc]);
                af[mt][1] = __float_as_uint(As_[(mr + 8) * 36 + k0 + lc]);
                af[mt][2] = __float_as_uint(As_[mr * 36 + k0 + lc + 4]);
                af[mt][3] = __float_as_uint(As_[(mr + 8) * 36 + k0 + lc + 4]);
            }
#pragma unroll
            for (int nt = 0; nt < 8; nt++) {
                uint32_t bf[2];
                int nc = n0 + nt * 8 + lr;
                bf[0] = __float_as_uint(Bs_[(k0 + lc) * 136 + nc]);
                bf[1] = __float_as_uint(Bs_[(k0 + lc + 4) * 136 + nc]);
                mma_tf32(acc[0][nt], af[0], bf);
                mma_tf32(acc[1][nt], af[1], bf);
            }
        }

        rbuf = (rbuf + 1) % 3;
        wbuf = (wbuf + 1) % 3;
    }

#pragma unroll
    for (int mt = 0; mt < 2; mt++) {
#pragma unroll
        for (int half = 0; half < 2; half++) {
            int row = bm + m0 + mt * 16 + lr + half * 8;
            float* Crow = C + (size_t)row * N + bn;
            const float* Rrow = (EPI >= 2) ? (res + (size_t)row * N + bn) : nullptr;
#pragma unroll
            for (int nt = 0; nt < 8; nt++) {
                int col = n0 + nt * 8 + lc * 2;
                float2 v = make_float2(acc[mt][nt][half * 2], acc[mt][nt][half * 2 + 1]);
                if (EPI == 1 || EPI == 3) {
                    float2 bb = *(const float2*)(bias + bn + col);
                    v.x += bb.x; v.y += bb.y;
                }
                if (EPI == 1) { v.x = fmaxf(v.x, 0.f); v.y = fmaxf(v.y, 0.f); }
                if (EPI >= 2) {
                    float2 rr = *(const float2*)(Rrow + col);
                    v.x += rr.x; v.y += rr.y;
                }
                *(float2*)&Crow[col] = v;
            }
        }
    }
}

// ---------------- tensor-core flash attention, 64q x 64k (R6 single-buffer) ---
// grid: (QLEN/64, BSZ, NH), 256 threads (8 warps).
#define AT_KS 68
#define AT_VS 72
#define AT_SS 68
#define AT_QS 68
#define AT_KS_OFF 0
#define AT_VS_OFF (64 * AT_KS)
#define AT_SS_OFF (AT_VS_OFF + 64 * AT_VS)
#define AT_ML_OFF (AT_SS_OFF + 64 * AT_SS)
#define AT_SMEM ((AT_ML_OFF + 192) * 4)          /* 54016 bytes */

__global__ __launch_bounds__(256)
void attn_tc_kernel(const float* __restrict__ Q, const float* __restrict__ KV,
                    float* __restrict__ Vout) {
    extern __shared__ __align__(16) float smf[];
    float* Ks  = smf + AT_KS_OFF;
    float* Vs  = smf + AT_VS_OFF;
    float* Ss  = smf + AT_SS_OFF;
    float* m_s = smf + AT_ML_OFF;
    float* l_s = m_s + 64;
    float* al_s = m_s + 128;

    const int qb = blockIdx.x, b = blockIdx.y, hh = blockIdx.z;
    const int t = threadIdx.x, lane = t & 31, warp = t >> 5;
    const int lr = lane >> 2, lc = lane & 3;

    const int kb2 = (warp & 1) * 32;     // QK: kj half
    const int nq0 = (warp >> 1) * 16;    // QK: q columns
    const int mq0 = (warp & 3) * 16;     // PV: q rows
    const int nd0 = (warp >> 2) * 32;    // PV: d cols
    const int kjA = t >> 4;              // KV staging rows kjA + 16s
    const int d4A = (t & 15) * 4;

    const int nTiles = 17 + qb;
    const int lastTile = nTiles - 1;

    // ---- prologue: Q (tf32) into Ss overlay (stride 68, float4-aligned)
    float* Qs = Ss;
    for (int idx = t; idx < 64 * 16; idx += 256) {
        int qi = idx >> 4, d4 = (idx & 15) * 4;
        float4 v = *(const float4*)&Q[((size_t)((qb * 64 + qi) * BSZ + b)) * DMODEL
                                      + hh * DHEAD + d4];
        *(float4*)&Qs[qi * AT_QS + d4] = tf4(v);
    }
    if (t < 64) { m_s[t] = -INFINITY; l_s[t] = 0.0f; }
    __syncthreads();

    // persistent Q fragments
    uint32_t qf[2][8][2];
#pragma unroll
    for (int nt = 0; nt < 2; nt++)
#pragma unroll
        for (int c = 0; c < 8; c++) {
            int qcol = nq0 + nt * 8 + lr;
            qf[nt][c][0] = __float_as_uint(Qs[qcol * AT_QS + c * 8 + lc]);
            qf[nt][c][1] = __float_as_uint(Qs[qcol * AT_QS + c * 8 + lc + 4]);
        }
    __syncthreads();   // all qf reads done before Ss is reused

    float oacc[4][4];
#pragma unroll
    for (int i = 0; i < 4; i++)
#pragma unroll
        for (int j = 0; j < 4; j++) oacc[i][j] = 0.0f;

    // prologue: KV tile 0 into registers
    float4 kr[4], vr[4];
#pragma unroll
    for (int s = 0; s < 4; s++) {
        size_t ba = ((size_t)(kjA + 16 * s) * BSZ + b) * (2 * DMODEL) + hh * DHEAD + d4A;
        kr[s] = *(const float4*)&KV[ba];
        vr[s] = *(const float4*)&KV[ba + DMODEL];
    }

    for (int tile = 0; tile < nTiles; tile++) {
        const int j0 = tile * 64;
        __syncthreads();   // previous tile's readers of Ks/Vs/Ss are done

        // stage registers -> smem (tf32), float4 stores
#pragma unroll
        for (int s = 0; s < 4; s++) {
            *(float4*)&Ks[(kjA + 16 * s) * AT_KS + d4A] = tf4(kr[s]);
            *(float4*)&Vs[(kjA + 16 * s) * AT_VS + d4A] = tf4(vr[s]);
        }
        // prefetch next tile (latency hides under compute)
        if (tile + 1 < nTiles) {
#pragma unroll
            for (int s = 0; s < 4; s++) {
                size_t ba = ((size_t)(j0 + 64 + kjA + 16 * s) * BSZ + b) * (2 * DMODEL)
                            + hh * DHEAD + d4A;
                kr[s] = *(const float4*)&KV[ba];
                vr[s] = *(const float4*)&KV[ba + DMODEL];
            }
        }
        __syncthreads();

        // S^T = K @ Q^T : 2 kj-tiles x 2 q-tiles per warp
        float sacc[2][2][4];
#pragma unroll
        for (int i = 0; i < 2; i++)
#pragma unroll
            for (int j = 0; j < 2; j++)
#pragma unroll
                for (int r = 0; r < 4; r++) sacc[i][j][r] = 0.0f;
#pragma unroll
        for (int mt2 = 0; mt2 < 2; mt2++) {
#pragma unroll
            for (int c = 0; c < 8; c++) {
                uint32_t af[4];
                int kr0 = (kb2 + mt2 * 16 + lr) * AT_KS;
                af[0] = __float_as_uint(Ks[kr0 + c * 8 + lc]);
                af[1] = __float_as_uint(Ks[kr0 + 8 * AT_KS + c * 8 + lc]);
                af[2] = __float_as_uint(Ks[kr0 + c * 8 + lc + 4]);
                af[3] = __float_as_uint(Ks[kr0 + 8 * AT_KS + c * 8 + lc + 4]);
                mma_tf32(sacc[mt2][0], af, qf[0][c]);
                mma_tf32(sacc[mt2][1], af, qf[1][c]);
            }
        }
        const bool maskTile = (tile == lastTile);
#pragma unroll
        for (int mt2 = 0; mt2 < 2; mt2++)
#pragma unroll
            for (int nt = 0; nt < 2; nt++)
#pragma unroll
                for (int i = 0; i < 4; i++) {
                    int kjl = kb2 + mt2 * 16 + lr + ((i >> 1) ? 8 : 0);
                    int ql  = nq0 + nt * 8 + 2 * lc + (i & 1);
                    float v = sacc[mt2][nt][i] * 0.125f;
                    if (maskTile && (j0 + kjl > MLEN + qb * 64 + ql)) v = -INFINITY;
                    Ss[ql * AT_SS + kjl] = v;
                }
        __syncthreads();

        // online softmax over 64 keys
        {
            int srow = t >> 2, sq = t & 3;
            float sv[16];
            float mx = -INFINITY;
#pragma unroll
            for (int j = 0; j < 16; j++) {
                sv[j] = Ss[srow * AT_SS + 4 * j + sq];
                mx = fmaxf(mx, sv[j]);
            }
            mx = fmaxf(mx, __shfl_xor_sync(0xffffffffu, mx, 1));
            mx = fmaxf(mx, __shfl_xor_sync(0xffffffffu, mx, 2));
            float mOld = m_s[srow];
            float mNew = fmaxf(mOld, mx);
            float al   = expf(mOld - mNew);
            float sum = 0.0f;
#pragma unroll
            for (int j = 0; j < 16; j++) {
                float p = expf(sv[j] - mNew);
                Ss[srow * AT_SS + 4 * j + sq] = __uint_as_float(f2tf(p));
                sum += p;
            }
            sum += __shfl_xor_sync(0xffffffffu, sum, 1);
            sum += __shfl_xor_sync(0xffffffffu, sum, 2);
            if (sq == 0) { m_s[srow] = mNew; l_s[srow] = l_s[srow] * al + sum; al_s[srow] = al; }
        }
        __syncthreads();

        // O += P @ V : 8 kj-chunks
        float a0 = al_s[mq0 + lr], a1 = al_s[mq0 + 8 + lr];
#pragma unroll
        for (int nt = 0; nt < 4; nt++) {
            oacc[nt][0] *= a0; oacc[nt][1] *= a0;
            oacc[nt][2] *= a1; oacc[nt][3] *= a1;
        }
#pragma unroll
        for (int c = 0; c < 8; c++) {
            uint32_t af[4];
            int pr0 = (mq0 + lr) * AT_SS;
            af[0] = __float_as_uint(Ss[pr0 + c * 8 + lc]);
            af[1] = __float_as_uint(Ss[pr0 + 8 * AT_SS + c * 8 + lc]);
            af[2] = __float_as_uint(Ss[pr0 + c * 8 + lc + 4]);
            af[3] = __float_as_uint(Ss[pr0 + 8 * AT_SS + c * 8 + lc + 4]);
#pragma unroll
            for (int nt = 0; nt < 4; nt++) {
                uint32_t bfv[2];
                bfv[0] = __float_as_uint(Vs[(c * 8 + lc) * AT_VS + nd0 + nt * 8 + lr]);
                bfv[1] = __float_as_uint(Vs[(c * 8 + lc + 4) * AT_VS + nd0 + nt * 8 + lr]);
                mma_tf32(oacc[nt], af, bfv);
            }
        }
    }

    // final normalize + store
#pragma unroll
    for (int half = 0; half < 2; half++) {
        int q = mq0 + lr + half * 8;
        float invl = 1.0f / l_s[q];
        float* orow = &Vout[((size_t)((qb * 64 + q) * BSZ + b)) * DMODEL + hh * DHEAD];
#pragma unroll
        for (int nt = 0; nt < 4; nt++) {
            float2 v = make_float2(oacc[nt][half * 2] * invl, oacc[nt][half * 2 + 1] * invl);
            *(float2*)&orow[nd0 + nt * 8 + 2 * lc] = v;
        }
    }
}

// ---------------- layernorm ---------------------------------------------------
__global__ __launch_bounds__(128)
void ln_kernel(const float* __restrict__ x, const float* __restrict__ g,
               const float* __restrict__ bparm, float* __restrict__ out) {
    const int row = blockIdx.x;
    const int t = threadIdx.x;
    float4 v = ((const float4*)(x + (size_t)row * DMODEL))[t];
    float s  = v.x + v.y + v.z + v.w;
    float s2 = fmaf(v.x, v.x, fmaf(v.y, v.y, fmaf(v.z, v.z, v.w * v.w)));
#pragma unroll
    for (int o = 16; o > 0; o >>= 1) {
        s  += __shfl_down_sync(0xffffffffu, s, o);
        s2 += __shfl_down_sync(0xffffffffu, s2, o);
    }
    __shared__ float ss[4], ss2[4];
    int w = t >> 5;
    if ((t & 31) == 0) { ss[w] = s; ss2[w] = s2; }
    __syncthreads();
    float tot  = ss[0] + ss[1] + ss[2] + ss[3];
    float tot2 = ss2[0] + ss2[1] + ss2[2] + ss2[3];
    float mu  = tot * (1.0f / DMODEL);
    float var = tot2 * (1.0f / DMODEL) - mu * mu;
    float rs  = rsqrtf(var + 1e-5f);
    float4 gg = ((const float4*)g)[t];
    float4 bb = ((const float4*)bparm)[t];
    float4 o;
    o.x = (v.x - mu) * rs * gg.x + bb.x;
    o.y = (v.y - mu) * rs * gg.y + bb.y;
    o.z = (v.z - mu) * rs * gg.z + bb.z;
    o.w = (v.w - mu) * rs * gg.w + bb.w;
    ((float4*)(out + (size_t)row * DMODEL))[t] = o;
}

// ---------------- launch ------------------------------------------------------
extern "C" void kernel_launch(void* const* d_in, const int* in_sizes, int n_in,
                              void* d_out, int out_size) {
    const int*   inp  = (const int*)d_in[0];
    const float* emb  = (const float*)d_in[1];
    const float* mems = (const float*)d_in[2];
    const float* Wq   = (const float*)d_in[3];
    const float* Wkv  = (const float*)d_in[4];
    const float* Wo   = (const float*)d_in[5];
    const float* ln1g = (const float*)d_in[6];
    const float* ln1b = (const float*)d_in[7];
    const float* W1   = (const float*)d_in[8];
    const float* b1   = (const float*)d_in[9];
    const float* W2   = (const float*)d_in[10];
    const float* b2   = (const float*)d_in[11];
    const float* ln2g = (const float*)d_in[12];
    const float* ln2b = (const float*)d_in[13];
    float* out = (float*)d_out;

    float *h, *c, *q, *kv, *vec, *ff, *tmp;
    cudaGetSymbolAddress((void**)&h,   g_h);
    cudaGetSymbolAddress((void**)&c,   g_c);
    cudaGetSymbolAddress((void**)&q,   g_q);
    cudaGetSymbolAddress((void**)&kv,  g_kv);
    cudaGetSymbolAddress((void**)&vec, g_vec);
    cudaGetSymbolAddress((void**)&ff,  g_ff);
    cudaGetSymbolAddress((void**)&tmp, g_tmp);

    cudaFuncSetAttribute(gemm_tf32_kernel<0>, cudaFuncAttributeMaxDynamicSharedMemorySize, G2_SMEM);
    cudaFuncSetAttribute(gemm_tf32_kernel<1>, cudaFuncAttributeMaxDynamicSharedMemorySize, G2_SMEM);
    cudaFuncSetAttribute(gemm_tf32_kernel<2>, cudaFuncAttributeMaxDynamicSharedMemorySize, G2_SMEM);
    cudaFuncSetAttribute(gemm_tf32_kernel<3>, cudaFuncAttributeMaxDynamicSharedMemorySize, G2_SMEM);
    cudaFuncSetAttribute(attn_tc_kernel, cudaFuncAttributeMaxDynamicSharedMemorySize, AT_SMEM);

    embed_kernel<<<(MROWS * DMODEL + 255) / 256, 256>>>(inp, emb, h);

    for (int l = 0; l < NLAYER; l++) {
        concat_kernel<<<(CROWS * DMODEL / 4 + 255) / 256, 256>>>(
            mems + (size_t)l * MLEN * BSZ * DMODEL, h, c);

        gemm_tf32_kernel<0><<<dim3(DMODEL / 128, MROWS / 128), 256, G2_SMEM>>>(
            h, Wq + (size_t)l * DMODEL * DMODEL, q,
            MROWS, DMODEL, DMODEL, nullptr, nullptr);

        gemm_tf32_kernel<0><<<dim3(2 * DMODEL / 128, CROWS / 128), 256, G2_SMEM>>>(
            c, Wkv + (size_t)l * DMODEL * 2 * DMODEL, kv,
            CROWS, 2 * DMODEL, DMODEL, nullptr, nullptr);

        attn_tc_kernel<<<dim3(QLEN / 64, BSZ, NH), 256, AT_SMEM>>>(q, kv, vec);

        gemm_tf32_kernel<2><<<dim3(DMODEL / 128, MROWS / 128), 256, G2_SMEM>>>(
            vec, Wo + (size_t)l * DMODEL * DMODEL, tmp,
            MROWS, DMODEL, DMODEL, nullptr, h);

        ln_kernel<<<MROWS, 128>>>(tmp, ln1g + l * DMODEL, ln1b + l * DMODEL, h);

        gemm_tf32_kernel<1><<<dim3(DFF / 128, MROWS / 128), 256, G2_SMEM>>>(
            h, W1 + (size_t)l * DMODEL * DFF, ff,
            MROWS, DFF, DMODEL, b1 + l * DFF, nullptr);

        gemm_tf32_kernel<3><<<dim3(DMODEL / 128, MROWS / 128), 256, G2_SMEM>>>(
            ff, W2 + (size_t)l * DFF * DMODEL, tmp,
            MROWS, DMODEL, DFF, b2 + l * DMODEL, h);

        ln_kernel<<<MROWS, 128>>>(tmp, ln2g + l * DMODEL, ln2b + l * DMODEL,
                                  (l == NLAYER - 1) ? out : h);
    }
}

// round 16
// speedup vs baseline: 1.5409x; 1.0985x over previous
#include <cuda_runtime.h>
#include <math.h>
#include <stdint.h>

#define QLEN 1024
#define MLEN 1024
#define BSZ 4
#define DMODEL 512
#define NH 8
#define DHEAD 64
#define DFF 2048
#define NLAYER 3
#define KLEN (QLEN + MLEN)
#define MROWS (QLEN * BSZ)   /* 4096 */
#define CROWS (KLEN * BSZ)   /* 8192 */

// ---------------- scratch (device globals; no allocation allowed) -------------
static __device__ float g_h[MROWS * DMODEL];
static __device__ float g_c[CROWS * DMODEL];
static __device__ float g_q[MROWS * DMODEL];
static __device__ float g_kv[CROWS * 2 * DMODEL];
static __device__ float g_vec[MROWS * DMODEL];
static __device__ float g_ff[MROWS * DFF];
static __device__ float g_tmp[MROWS * DMODEL];

// ---------------- helpers ------------------------------------------------------
__device__ __forceinline__ uint32_t f2tf(float x) {
    uint32_t r;
    asm("cvt.rna.tf32.f32 %0, %1;" : "=r"(r) : "f"(x));
    return r;
}
__device__ __forceinline__ float4 tf4(float4 v) {
    return make_float4(__uint_as_float(f2tf(v.x)), __uint_as_float(f2tf(v.y)),
                       __uint_as_float(f2tf(v.z)), __uint_as_float(f2tf(v.w)));
}

__device__ __forceinline__ void mma_tf32(float* c, const uint32_t* a, const uint32_t* b) {
    asm volatile(
        "mma.sync.aligned.m16n8k8.row.col.f32.tf32.tf32.f32 "
        "{%0,%1,%2,%3}, {%4,%5,%6,%7}, {%8,%9}, {%0,%1,%2,%3};"
        : "+f"(c[0]), "+f"(c[1]), "+f"(c[2]), "+f"(c[3])
        : "r"(a[0]), "r"(a[1]), "r"(a[2]), "r"(a[3]), "r"(b[0]), "r"(b[1]));
}

__device__ __forceinline__ void cp16(void* smem, const void* gmem) {
    uint32_t s = (uint32_t)__cvta_generic_to_shared(smem);
    asm volatile("cp.async.ca.shared.global [%0], [%1], 16;\n" :: "r"(s), "l"(gmem));
}
#define CP_COMMIT() asm volatile("cp.async.commit_group;\n" ::: "memory")
#define CP_WAIT1()  asm volatile("cp.async.wait_group 1;\n" ::: "memory")
#define CP_WAIT0()  asm volatile("cp.async.wait_group 0;\n" ::: "memory")

// ---------------- embedding + sinusoidal position -----------------------------
__global__ void embed_kernel(const int* __restrict__ inp,
                             const float* __restrict__ emb,
                             float* __restrict__ h) {
    int idx = blockIdx.x * blockDim.x + threadIdx.x;
    if (idx >= MROWS * DMODEL) return;
    int d   = idx & (DMODEL - 1);
    int row = idx >> 9;
    int i   = row >> 2;
    int tok = inp[row];
    float val = emb[(size_t)tok * DMODEL + d] * 22.62741699796952f;
    float pos = (float)(QLEN - 1 - i);
    int j = (d < DMODEL / 2) ? d : d - DMODEL / 2;
    float f = powf(10000.0f, -(float)j * (1.0f / 256.0f));
    float ang = pos * f;
    val += (d < DMODEL / 2) ? sinf(ang) : cosf(ang);
    h[idx] = val;
}

// ---------------- concat ------------------------------------------------------
__global__ void concat_kernel(const float* __restrict__ mems_l,
                              const float* __restrict__ h,
                              float* __restrict__ c) {
    const int nhalf = MROWS * DMODEL / 4;
    int idx = blockIdx.x * blockDim.x + threadIdx.x;
    if (idx >= 2 * nhalf) return;
    float4 v = (idx < nhalf) ? ((const float4*)mems_l)[idx]
                             : ((const float4*)h)[idx - nhalf];
    ((float4*)c)[idx] = v;
}

// ---------------- TF32 GEMM, 3-stage cp.async ring: 128x128x16 (R6 proven) ----
// EPI: 0 = none, 1 = relu(x + bias), 2 = x + res, 3 = x + bias + res
#define G_ASZ  (128 * 20)
#define G_BSZ  (16 * 136)
#define G_STG  (G_ASZ + G_BSZ)
#define G_SMEM (3 * G_STG * 4)     /* 56832 bytes */

template <int EPI>
__global__ __launch_bounds__(256, 2)
void gemm_tf32_kernel(const float* __restrict__ A, const float* __restrict__ B,
                      float* __restrict__ C, int M, int N, int K,
                      const float* __restrict__ bias, const float* __restrict__ res) {
    extern __shared__ __align__(16) float sm[];

    const int t    = threadIdx.x;
    const int lane = t & 31;
    const int warp = t >> 5;
    const int wm   = warp & 3;
    const int wn   = warp >> 2;
    const int lr   = lane >> 2;
    const int lc   = lane & 3;
    const int bm   = blockIdx.y * 128, bn = blockIdx.x * 128;
    const int m0   = wm * 32, n0 = wn * 64;

    const int amA = t >> 2;
    const int akA = (t & 3) * 4;
    const int bkB = t >> 5;
    const int bnB = (t & 31) * 4;

    const float* Aptr = A + (size_t)(bm + amA) * K + akA;
    const float* Bptr = B + (size_t)bkB * N + bn + bnB;
    const size_t Astep64 = (size_t)64 * K;
    const size_t Bstep8  = (size_t)8 * N;

    const int aOff0 = amA * 20 + akA;
    const int aOff1 = (amA + 64) * 20 + akA;
    const int bOff0 = G_ASZ + bkB * 136 + bnB;
    const int bOff1 = G_ASZ + (bkB + 8) * 136 + bnB;

    float acc[2][8][4];
#pragma unroll
    for (int i = 0; i < 2; i++)
#pragma unroll
        for (int j = 0; j < 8; j++)
#pragma unroll
            for (int r = 0; r < 4; r++) acc[i][j][r] = 0.0f;

    const int KB = K >> 4;

#pragma unroll
    for (int s = 0; s < 2; s++) {
        float* st = sm + s * G_STG;
        const float* Ap = Aptr + s * 16;
        const float* Bp = Bptr + (size_t)s * 16 * N;
        cp16(st + aOff0, Ap);
        cp16(st + aOff1, Ap + Astep64);
        cp16(st + bOff0, Bp);
        cp16(st + bOff1, Bp + Bstep8);
        CP_COMMIT();
    }

    int rbuf = 0, wbuf = 2;
    for (int kb = 0; kb < KB; kb++) {
        if (kb + 1 < KB) CP_WAIT1(); else CP_WAIT0();
        __syncthreads();

        if (kb + 2 < KB) {
            float* st = sm + wbuf * G_STG;
            const float* Ap = Aptr + (kb + 2) * 16;
            const float* Bp = Bptr + (size_t)(kb + 2) * 16 * N;
            cp16(st + aOff0, Ap);
            cp16(st + aOff1, Ap + Astep64);
            cp16(st + bOff0, Bp);
            cp16(st + bOff1, Bp + Bstep8);
            CP_COMMIT();
        }

        const float* As_ = sm + rbuf * G_STG;
        const float* Bs_ = As_ + G_ASZ;

        uint32_t af[2][2][4];
        uint32_t bf[2][8][2];
#pragma unroll
        for (int ks = 0; ks < 2; ks++) {
            const int k0 = ks * 8;
#pragma unroll
            for (int mt = 0; mt < 2; mt++) {
                int mr = m0 + mt * 16 + lr;
                af[ks][mt][0] = __float_as_uint(As_[mr * 20 + k0 + lc]);
                af[ks][mt][1] = __float_as_uint(As_[(mr + 8) * 20 + k0 + lc]);
                af[ks][mt][2] = __float_as_uint(As_[mr * 20 + k0 + lc + 4]);
                af[ks][mt][3] = __float_as_uint(As_[(mr + 8) * 20 + k0 + lc + 4]);
            }
#pragma unroll
            for (int nt = 0; nt < 8; nt++) {
                int nc = n0 + nt * 8 + lr;
                bf[ks][nt][0] = __float_as_uint(Bs_[(k0 + lc) * 136 + nc]);
                bf[ks][nt][1] = __float_as_uint(Bs_[(k0 + lc + 4) * 136 + nc]);
            }
        }
#pragma unroll
        for (int ks = 0; ks < 2; ks++)
#pragma unroll
            for (int nt = 0; nt < 8; nt++) {
                mma_tf32(acc[0][nt], af[ks][0], bf[ks][nt]);
                mma_tf32(acc[1][nt], af[ks][1], bf[ks][nt]);
            }

        rbuf = (rbuf + 1) % 3;
        wbuf = (wbuf + 1) % 3;
    }

#pragma unroll
    for (int mt = 0; mt < 2; mt++) {
#pragma unroll
        for (int half = 0; half < 2; half++) {
            int row = bm + m0 + mt * 16 + lr + half * 8;
            float* Crow = C + (size_t)row * N + bn;
            const float* Rrow = (EPI >= 2) ? (res + (size_t)row * N + bn) : nullptr;
#pragma unroll
            for (int nt = 0; nt < 8; nt++) {
                int col = n0 + nt * 8 + lc * 2;
                float2 v = make_float2(acc[mt][nt][half * 2], acc[mt][nt][half * 2 + 1]);
                if (EPI == 1 || EPI == 3) {
                    float2 bb = *(const float2*)(bias + bn + col);
                    v.x += bb.x; v.y += bb.y;
                }
                if (EPI == 1) { v.x = fmaxf(v.x, 0.f); v.y = fmaxf(v.y, 0.f); }
                if (EPI >= 2) {
                    float2 rr = *(const float2*)(Rrow + col);
                    v.x += rr.x; v.y += rr.y;
                }
                *(float2*)&Crow[col] = v;
            }
        }
    }
}

// ---------------- tensor-core flash attention, 64q x 64k, cp.async KV --------
// grid: (QLEN/64, BSZ, NH), 256 threads (8 warps). Double-buffered K/V via
// cp.async (raw fp32 bits read as tf32 by mma). 3 barriers per tile.
#define AT_KS 68
#define AT_VS 72
#define AT_SS 68
#define AT_QS 68
#define AT_KS_OFF 0                              /* Ks[2][64*68] */
#define AT_VS_OFF (2 * 64 * AT_KS)               /* Vs[2][64*72] */
#define AT_SS_OFF (AT_VS_OFF + 2 * 64 * AT_VS)   /* Ss[64*68]    */
#define AT_ML_OFF (AT_SS_OFF + 64 * AT_SS)
#define AT_SMEM ((AT_ML_OFF + 192) * 4)          /* 89856 bytes */

__global__ __launch_bounds__(256)
void attn_tc_kernel(const float* __restrict__ Q, const float* __restrict__ KV,
                    float* __restrict__ Vout) {
    extern __shared__ __align__(16) float smf[];
    float* Ks0 = smf + AT_KS_OFF;
    float* Ks1 = smf + AT_KS_OFF + 64 * AT_KS;
    float* Vs0 = smf + AT_VS_OFF;
    float* Vs1 = smf + AT_VS_OFF + 64 * AT_VS;
    float* Ss  = smf + AT_SS_OFF;
    float* m_s = smf + AT_ML_OFF;
    float* l_s = m_s + 64;
    float* al_s = m_s + 128;

    const int qb = blockIdx.x, b = blockIdx.y, hh = blockIdx.z;
    const int t = threadIdx.x, lane = t & 31, warp = t >> 5;
    const int lr = lane >> 2, lc = lane & 3;

    const int kb2 = (warp & 1) * 32;     // QK: kj half
    const int nq0 = (warp >> 1) * 16;    // QK: q columns
    const int mq0 = (warp & 3) * 16;     // PV: q rows
    const int nd0 = (warp >> 2) * 32;    // PV: d cols
    const int kjA = t >> 4;              // KV staging rows kjA + 16s
    const int d4A = (t & 15) * 4;

    const int nTiles = 17 + qb;
    const int lastTile = nTiles - 1;

    // issue cp.async for KV tile 0 into buffer 0 (overlaps with Q staging)
#pragma unroll
    for (int s = 0; s < 4; s++) {
        const float* base = &KV[((size_t)(kjA + 16 * s) * BSZ + b) * (2 * DMODEL)
                                + hh * DHEAD + d4A];
        cp16(&Ks0[(kjA + 16 * s) * AT_KS + d4A], base);
        cp16(&Vs0[(kjA + 16 * s) * AT_VS + d4A], base + DMODEL);
    }
    CP_COMMIT();

    // Q (tf32-rounded) into Ss overlay (stride 68, float4-aligned)
    float* Qs = Ss;
    for (int idx = t; idx < 64 * 16; idx += 256) {
        int qi = idx >> 4, d4 = (idx & 15) * 4;
        float4 v = *(const float4*)&Q[((size_t)((qb * 64 + qi) * BSZ + b)) * DMODEL
                                      + hh * DHEAD + d4];
        *(float4*)&Qs[qi * AT_QS + d4] = tf4(v);
    }
    if (t < 64) { m_s[t] = -INFINITY; l_s[t] = 0.0f; }
    __syncthreads();

    // persistent Q fragments
    uint32_t qf[2][8][2];
#pragma unroll
    for (int nt = 0; nt < 2; nt++)
#pragma unroll
        for (int c = 0; c < 8; c++) {
            int qcol = nq0 + nt * 8 + lr;
            qf[nt][c][0] = __float_as_uint(Qs[qcol * AT_QS + c * 8 + lc]);
            qf[nt][c][1] = __float_as_uint(Qs[qcol * AT_QS + c * 8 + lc + 4]);
        }

    float oacc[4][4];
#pragma unroll
    for (int i = 0; i < 4; i++)
#pragma unroll
        for (int j = 0; j < 4; j++) oacc[i][j] = 0.0f;

    int buf = 0;
    for (int tile = 0; tile < nTiles; tile++) {
        const int j0 = tile * 64;
        const float* Ks = buf ? Ks1 : Ks0;
        const float* Vs = buf ? Vs1 : Vs0;
        float* KsN = buf ? Ks0 : Ks1;
        float* VsN = buf ? Vs0 : Vs1;

        CP_WAIT0();
        __syncthreads();   // (1) KV[buf] ready; prev PV readers of buf^1 done;
                           //     on tile 0 also: qf extraction done before Ss reuse

        // issue cp.async for next tile into the other buffer
        if (tile + 1 < nTiles) {
#pragma unroll
            for (int s = 0; s < 4; s++) {
                const float* base = &KV[((size_t)(j0 + 64 + kjA + 16 * s) * BSZ + b)
                                        * (2 * DMODEL) + hh * DHEAD + d4A];
                cp16(&KsN[(kjA + 16 * s) * AT_KS + d4A], base);
                cp16(&VsN[(kjA + 16 * s) * AT_VS + d4A], base + DMODEL);
            }
            CP_COMMIT();
        }

        // S^T = K @ Q^T : 2 kj-tiles x 2 q-tiles per warp
        float sacc[2][2][4];
#pragma unroll
        for (int i = 0; i < 2; i++)
#pragma unroll
            for (int j = 0; j < 2; j++)
#pragma unroll
                for (int r = 0; r < 4; r++) sacc[i][j][r] = 0.0f;
#pragma unroll
        for (int mt2 = 0; mt2 < 2; mt2++) {
#pragma unroll
            for (int c = 0; c < 8; c++) {
                uint32_t af[4];
                int kr0 = (kb2 + mt2 * 16 + lr) * AT_KS;
                af[0] = __float_as_uint(Ks[kr0 + c * 8 + lc]);
                af[1] = __float_as_uint(Ks[kr0 + 8 * AT_KS + c * 8 + lc]);
                af[2] = __float_as_uint(Ks[kr0 + c * 8 + lc + 4]);
                af[3] = __float_as_uint(Ks[kr0 + 8 * AT_KS + c * 8 + lc + 4]);
                mma_tf32(sacc[mt2][0], af, qf[0][c]);
                mma_tf32(sacc[mt2][1], af, qf[1][c]);
            }
        }
        const bool maskTile = (tile == lastTile);
#pragma unroll
        for (int mt2 = 0; mt2 < 2; mt2++)
#pragma unroll
            for (int nt = 0; nt < 2; nt++)
#pragma unroll
                for (int i = 0; i < 4; i++) {
                    int kjl = kb2 + mt2 * 16 + lr + ((i >> 1) ? 8 : 0);
                    int ql  = nq0 + nt * 8 + 2 * lc + (i & 1);
                    float v = sacc[mt2][nt][i] * 0.125f;
                    if (maskTile && (j0 + kjl > MLEN + qb * 64 + ql)) v = -INFINITY;
                    Ss[ql * AT_SS + kjl] = v;
                }
        __syncthreads();   // (2) scores visible to softmax

        // online softmax over 64 keys
        {
            int srow = t >> 2, sq = t & 3;
            float sv[16];
            float mx = -INFINITY;
#pragma unroll
            for (int j = 0; j < 16; j++) {
                sv[j] = Ss[srow * AT_SS + 4 * j + sq];
                mx = fmaxf(mx, sv[j]);
            }
            mx = fmaxf(mx, __shfl_xor_sync(0xffffffffu, mx, 1));
            mx = fmaxf(mx, __shfl_xor_sync(0xffffffffu, mx, 2));
            float mOld = m_s[srow];
            float mNew = fmaxf(mOld, mx);
            float al   = expf(mOld - mNew);
            float sum = 0.0f;
#pragma unroll
            for (int j = 0; j < 16; j++) {
                float p = expf(sv[j] - mNew);
                Ss[srow * AT_SS + 4 * j + sq] = __uint_as_float(f2tf(p));
                sum += p;
            }
            sum += __shfl_xor_sync(0xffffffffu, sum, 1);
            sum += __shfl_xor_sync(0xffffffffu, sum, 2);
            if (sq == 0) { m_s[srow] = mNew; l_s[srow] = l_s[srow] * al + sum; al_s[srow] = al; }
        }
        __syncthreads();   // (3) probs + al visible to PV

        // O += P @ V : 8 kj-chunks
        float a0 = al_s[mq0 + lr], a1 = al_s[mq0 + 8 + lr];
#pragma unroll
        for (int nt = 0; nt < 4; nt++) {
            oacc[nt][0] *= a0; oacc[nt][1] *= a0;
            oacc[nt][2] *= a1; oacc[nt][3] *= a1;
        }
#pragma unroll
        for (int c = 0; c < 8; c++) {
            uint32_t af[4];
            int pr0 = (mq0 + lr) * AT_SS;
            af[0] = __float_as_uint(Ss[pr0 + c * 8 + lc]);
            af[1] = __float_as_uint(Ss[pr0 + 8 * AT_SS + c * 8 + lc]);
            af[2] = __float_as_uint(Ss[pr0 + c * 8 + lc + 4]);
            af[3] = __float_as_uint(Ss[pr0 + 8 * AT_SS + c * 8 + lc + 4]);
#pragma unroll
            for (int nt = 0; nt < 4; nt++) {
                uint32_t bfv[2];
                bfv[0] = __float_as_uint(Vs[(c * 8 + lc) * AT_VS + nd0 + nt * 8 + lr]);
                bfv[1] = __float_as_uint(Vs[(c * 8 + lc + 4) * AT_VS + nd0 + nt * 8 + lr]);
                mma_tf32(oacc[nt], af, bfv);
            }
        }
        buf ^= 1;
    }

    // final normalize + store
#pragma unroll
    for (int half = 0; half < 2; half++) {
        int q = mq0 + lr + half * 8;
        float invl = 1.0f / l_s[q];
        float* orow = &Vout[((size_t)((qb * 64 + q) * BSZ + b)) * DMODEL + hh * DHEAD];
#pragma unroll
        for (int nt = 0; nt < 4; nt++) {
            float2 v = make_float2(oacc[nt][half * 2] * invl, oacc[nt][half * 2 + 1] * invl);
            *(float2*)&orow[nd0 + nt * 8 + 2 * lc] = v;
        }
    }
}

// ---------------- layernorm ---------------------------------------------------
__global__ __launch_bounds__(128)
void ln_kernel(const float* __restrict__ x, const float* __restrict__ g,
               const float* __restrict__ bparm, float* __restrict__ out) {
    const int row = blockIdx.x;
    const int t = threadIdx.x;
    float4 v = ((const float4*)(x + (size_t)row * DMODEL))[t];
    float s  = v.x + v.y + v.z + v.w;
    float s2 = fmaf(v.x, v.x, fmaf(v.y, v.y, fmaf(v.z, v.z, v.w * v.w)));
#pragma unroll
    for (int o = 16; o > 0; o >>= 1) {
        s  += __shfl_down_sync(0xffffffffu, s, o);
        s2 += __shfl_down_sync(0xffffffffu, s2, o);
    }
    __shared__ float ss[4], ss2[4];
    int w = t >> 5;
    if ((t & 31) == 0) { ss[w] = s; ss2[w] = s2; }
    __syncthreads();
    float tot  = ss[0] + ss[1] + ss[2] + ss[3];
    float tot2 = ss2[0] + ss2[1] + ss2[2] + ss2[3];
    float mu  = tot * (1.0f / DMODEL);
    float var = tot2 * (1.0f / DMODEL) - mu * mu;
    float rs  = rsqrtf(var + 1e-5f);
    float4 gg = ((const float4*)g)[t];
    float4 bb = ((const float4*)bparm)[t];
    float4 o;
    o.x = (v.x - mu) * rs * gg.x + bb.x;
    o.y = (v.y - mu) * rs * gg.y + bb.y;
    o.z = (v.z - mu) * rs * gg.z + bb.z;
    o.w = (v.w - mu) * rs * gg.w + bb.w;
    ((float4*)(out + (size_t)row * DMODEL))[t] = o;
}

// ---------------- launch ------------------------------------------------------
extern "C" void kernel_launch(void* const* d_in, const int* in_sizes, int n_in,
                              void* d_out, int out_size) {
    const int*   inp  = (const int*)d_in[0];
    const float* emb  = (const float*)d_in[1];
    const float* mems = (const float*)d_in[2];
    const float* Wq   = (const float*)d_in[3];
    const float* Wkv  = (const float*)d_in[4];
    const float* Wo   = (const float*)d_in[5];
    const float* ln1g = (const float*)d_in[6];
    const float* ln1b = (const float*)d_in[7];
    const float* W1   = (const float*)d_in[8];
    const float* b1   = (const float*)d_in[9];
    const float* W2   = (const float*)d_in[10];
    const float* b2   = (const float*)d_in[11];
    const float* ln2g = (const float*)d_in[12];
    const float* ln2b = (const float*)d_in[13];
    float* out = (float*)d_out;

    float *h, *c, *q, *kv, *vec, *ff, *tmp;
    cudaGetSymbolAddress((void**)&h,   g_h);
    cudaGetSymbolAddress((void**)&c,   g_c);
    cudaGetSymbolAddress((void**)&q,   g_q);
    cudaGetSymbolAddress((void**)&kv,  g_kv);
    cudaGetSymbolAddress((void**)&vec, g_vec);
    cudaGetSymbolAddress((void**)&ff,  g_ff);
    cudaGetSymbolAddress((void**)&tmp, g_tmp);

    cudaFuncSetAttribute(gemm_tf32_kernel<0>, cudaFuncAttributeMaxDynamicSharedMemorySize, G_SMEM);
    cudaFuncSetAttribute(gemm_tf32_kernel<1>, cudaFuncAttributeMaxDynamicSharedMemorySize, G_SMEM);
    cudaFuncSetAttribute(gemm_tf32_kernel<2>, cudaFuncAttributeMaxDynamicSharedMemorySize, G_SMEM);
    cudaFuncSetAttribute(gemm_tf32_kernel<3>, cudaFuncAttributeMaxDynamicSharedMemorySize, G_SMEM);
    cudaFuncSetAttribute(attn_tc_kernel, cudaFuncAttributeMaxDynamicSharedMemorySize, AT_SMEM);

    embed_kernel<<<(MROWS * DMODEL + 255) / 256, 256>>>(inp, emb, h);

    for (int l = 0; l < NLAYER; l++) {
        concat_kernel<<<(CROWS * DMODEL / 4 + 255) / 256, 256>>>(
            mems + (size_t)l * MLEN * BSZ * DMODEL, h, c);

        gemm_tf32_kernel<0><<<dim3(DMODEL / 128, MROWS / 128), 256, G_SMEM>>>(
            h, Wq + (size_t)l * DMODEL * DMODEL, q,
            MROWS, DMODEL, DMODEL, nullptr, nullptr);

        gemm_tf32_kernel<0><<<dim3(2 * DMODEL / 128, CROWS / 128), 256, G_SMEM>>>(
            c, Wkv + (size_t)l * DMODEL * 2 * DMODEL, kv,
            CROWS, 2 * DMODEL, DMODEL, nullptr, nullptr);

        attn_tc_kernel<<<dim3(QLEN / 64, BSZ, NH), 256, AT_SMEM>>>(q, kv, vec);

        gemm_tf32_kernel<2><<<dim3(DMODEL / 128, MROWS / 128), 256, G_SMEM>>>(
            vec, Wo + (size_t)l * DMODEL * DMODEL, tmp,
            MROWS, DMODEL, DMODEL, nullptr, h);

        ln_kernel<<<MROWS, 128>>>(tmp, ln1g + l * DMODEL, ln1b + l * DMODEL, h);

        gemm_tf32_kernel<1><<<dim3(DFF / 128, MROWS / 128), 256, G_SMEM>>>(
            h, W1 + (size_t)l * DMODEL * DFF, ff,
            MROWS, DFF, DMODEL, b1 + l * DFF, nullptr);

        gemm_tf32_kernel<3><<<dim3(DMODEL / 128, MROWS / 128), 256, G_SMEM>>>(
            ff, W2 + (size_t)l * DFF * DMODEL, tmp,
            MROWS, DMODEL, DFF, b2 + l * DMODEL, h);

        ln_kernel<<<MROWS, 128>>>(tmp, ln2g + l * DMODEL, ln2b + l * DMODEL,
                                  (l == NLAYER - 1) ? out : h);
    }
}

// round 17
// speedup vs baseline: 1.5872x; 1.0300x over previous
#include <cuda_runtime.h>
#include <math.h>
#include <stdint.h>

#define QLEN 1024
#define MLEN 1024
#define BSZ 4
#define DMODEL 512
#define NH 8
#define DHEAD 64
#define DFF 2048
#define NLAYER 3
#define KLEN (QLEN + MLEN)
#define MROWS (QLEN * BSZ)   /* 4096 */
#define CROWS (KLEN * BSZ)   /* 8192 */

// ---------------- scratch (device globals; no allocation allowed) -------------
static __device__ float g_h[MROWS * DMODEL];
static __device__ float g_q[MROWS * DMODEL];
static __device__ float g_kv[CROWS * 2 * DMODEL];
static __device__ float g_vec[MROWS * DMODEL];
static __device__ float g_ff[MROWS * DFF];
static __device__ float g_tmp[MROWS * DMODEL];

// ---------------- helpers ------------------------------------------------------
__device__ __forceinline__ uint32_t f2tf(float x) {
    uint32_t r;
    asm("cvt.rna.tf32.f32 %0, %1;" : "=r"(r) : "f"(x));
    return r;
}
__device__ __forceinline__ float4 tf4(float4 v) {
    return make_float4(__uint_as_float(f2tf(v.x)), __uint_as_float(f2tf(v.y)),
                       __uint_as_float(f2tf(v.z)), __uint_as_float(f2tf(v.w)));
}

__device__ __forceinline__ void mma_tf32(float* c, const uint32_t* a, const uint32_t* b) {
    asm volatile(
        "mma.sync.aligned.m16n8k8.row.col.f32.tf32.tf32.f32 "
        "{%0,%1,%2,%3}, {%4,%5,%6,%7}, {%8,%9}, {%0,%1,%2,%3};"
        : "+f"(c[0]), "+f"(c[1]), "+f"(c[2]), "+f"(c[3])
        : "r"(a[0]), "r"(a[1]), "r"(a[2]), "r"(a[3]), "r"(b[0]), "r"(b[1]));
}

__device__ __forceinline__ void cp16(void* smem, const void* gmem) {
    uint32_t s = (uint32_t)__cvta_generic_to_shared(smem);
    asm volatile("cp.async.ca.shared.global [%0], [%1], 16;\n" :: "r"(s), "l"(gmem));
}
#define CP_COMMIT() asm volatile("cp.async.commit_group;\n" ::: "memory")
#define CP_WAIT1()  asm volatile("cp.async.wait_group 1;\n" ::: "memory")
#define CP_WAIT0()  asm volatile("cp.async.wait_group 0;\n" ::: "memory")

// ---------------- embedding + sinusoidal position -----------------------------
__global__ void embed_kernel(const int* __restrict__ inp,
                             const float* __restrict__ emb,
                             float* __restrict__ h) {
    int idx = blockIdx.x * blockDim.x + threadIdx.x;
    if (idx >= MROWS * DMODEL) return;
    int d   = idx & (DMODEL - 1);
    int row = idx >> 9;
    int i   = row >> 2;
    int tok = inp[row];
    float val = emb[(size_t)tok * DMODEL + d] * 22.62741699796952f;
    float pos = (float)(QLEN - 1 - i);
    int j = (d < DMODEL / 2) ? d : d - DMODEL / 2;
    float f = powf(10000.0f, -(float)j * (1.0f / 256.0f));
    float ang = pos * f;
    val += (d < DMODEL / 2) ? sinf(ang) : cosf(ang);
    h[idx] = val;
}

// ---------------- TF32 GEMM, 3-stage cp.async ring: 128x128x16 ----------------
// EPI: 0 = none, 1 = relu(x + bias), 2 = x + res, 3 = x + bias + res
// CONCAT: A rows < M_SPLIT come from A, rows >= M_SPLIT from A2 (row rebased).
#define G_ASZ  (128 * 20)
#define G_BSZ  (16 * 136)
#define G_STG  (G_ASZ + G_BSZ)
#define G_SMEM (3 * G_STG * 4)     /* 56832 bytes */

template <int EPI, int CONCAT>
__global__ __launch_bounds__(256, 2)
void gemm_tf32_kernel(const float* __restrict__ A, const float* __restrict__ A2,
                      int M_SPLIT,
                      const float* __restrict__ B,
                      float* __restrict__ C, int M, int N, int K,
                      const float* __restrict__ bias, const float* __restrict__ res) {
    extern __shared__ __align__(16) float sm[];

    const int t    = threadIdx.x;
    const int lane = t & 31;
    const int warp = t >> 5;
    const int wm   = warp & 3;
    const int wn   = warp >> 2;
    const int lr   = lane >> 2;
    const int lc   = lane & 3;
    const int bm   = blockIdx.y * 128, bn = blockIdx.x * 128;
    const int m0   = wm * 32, n0 = wn * 64;

    const int amA = t >> 2;
    const int akA = (t & 3) * 4;
    const int bkB = t >> 5;
    const int bnB = (t & 31) * 4;

    // per-thread A rows are fixed: pick source base once (concat fusion)
    const int rowA0 = bm + amA;          // first A row this thread loads
    const int rowA1 = bm + amA + 64;     // second
    const float* Aptr0;
    const float* Aptr1;
    if (CONCAT) {
        Aptr0 = (rowA0 < M_SPLIT) ? (A + (size_t)rowA0 * K + akA)
                                  : (A2 + (size_t)(rowA0 - M_SPLIT) * K + akA);
        Aptr1 = (rowA1 < M_SPLIT) ? (A + (size_t)rowA1 * K + akA)
                                  : (A2 + (size_t)(rowA1 - M_SPLIT) * K + akA);
    } else {
        Aptr0 = A + (size_t)rowA0 * K + akA;
        Aptr1 = A + (size_t)rowA1 * K + akA;
    }
    const float* Bptr = B + (size_t)bkB * N + bn + bnB;
    const size_t Bstep8 = (size_t)8 * N;

    const int aOff0 = amA * 20 + akA;
    const int aOff1 = (amA + 64) * 20 + akA;
    const int bOff0 = G_ASZ + bkB * 136 + bnB;
    const int bOff1 = G_ASZ + (bkB + 8) * 136 + bnB;

    float acc[2][8][4];
#pragma unroll
    for (int i = 0; i < 2; i++)
#pragma unroll
        for (int j = 0; j < 8; j++)
#pragma unroll
            for (int r = 0; r < 4; r++) acc[i][j][r] = 0.0f;

    const int KB = K >> 4;

#pragma unroll
    for (int s = 0; s < 2; s++) {
        float* st = sm + s * G_STG;
        const float* Bp = Bptr + (size_t)s * 16 * N;
        cp16(st + aOff0, Aptr0 + s * 16);
        cp16(st + aOff1, Aptr1 + s * 16);
        cp16(st + bOff0, Bp);
        cp16(st + bOff1, Bp + Bstep8);
        CP_COMMIT();
    }

    int rbuf = 0, wbuf = 2;
    for (int kb = 0; kb < KB; kb++) {
        if (kb + 1 < KB) CP_WAIT1(); else CP_WAIT0();
        __syncthreads();

        if (kb + 2 < KB) {
            float* st = sm + wbuf * G_STG;
            const float* Bp = Bptr + (size_t)(kb + 2) * 16 * N;
            cp16(st + aOff0, Aptr0 + (kb + 2) * 16);
            cp16(st + aOff1, Aptr1 + (kb + 2) * 16);
            cp16(st + bOff0, Bp);
            cp16(st + bOff1, Bp + Bstep8);
            CP_COMMIT();
        }

        const float* As_ = sm + rbuf * G_STG;
        const float* Bs_ = As_ + G_ASZ;

        uint32_t af[2][2][4];
        uint32_t bf[2][8][2];
#pragma unroll
        for (int ks = 0; ks < 2; ks++) {
            const int k0 = ks * 8;
#pragma unroll
            for (int mt = 0; mt < 2; mt++) {
                int mr = m0 + mt * 16 + lr;
                af[ks][mt][0] = __float_as_uint(As_[mr * 20 + k0 + lc]);
                af[ks][mt][1] = __float_as_uint(As_[(mr + 8) * 20 + k0 + lc]);
                af[ks][mt][2] = __float_as_uint(As_[mr * 20 + k0 + lc + 4]);
                af[ks][mt][3] = __float_as_uint(As_[(mr + 8) * 20 + k0 + lc + 4]);
            }
#pragma unroll
            for (int nt = 0; nt < 8; nt++) {
                int nc = n0 + nt * 8 + lr;
                bf[ks][nt][0] = __float_as_uint(Bs_[(k0 + lc) * 136 + nc]);
                bf[ks][nt][1] = __float_as_uint(Bs_[(k0 + lc + 4) * 136 + nc]);
            }
        }
#pragma unroll
        for (int ks = 0; ks < 2; ks++)
#pragma unroll
            for (int nt = 0; nt < 8; nt++) {
                mma_tf32(acc[0][nt], af[ks][0], bf[ks][nt]);
                mma_tf32(acc[1][nt], af[ks][1], bf[ks][nt]);
            }

        rbuf = (rbuf + 1) % 3;
        wbuf = (wbuf + 1) % 3;
    }

#pragma unroll
    for (int mt = 0; mt < 2; mt++) {
#pragma unroll
        for (int half = 0; half < 2; half++) {
            int row = bm + m0 + mt * 16 + lr + half * 8;
            float* Crow = C + (size_t)row * N + bn;
            const float* Rrow = (EPI >= 2) ? (res + (size_t)row * N + bn) : nullptr;
#pragma unroll
            for (int nt = 0; nt < 8; nt++) {
                int col = n0 + nt * 8 + lc * 2;
                float2 v = make_float2(acc[mt][nt][half * 2], acc[mt][nt][half * 2 + 1]);
                if (EPI == 1 || EPI == 3) {
                    float2 bb = *(const float2*)(bias + bn + col);
                    v.x += bb.x; v.y += bb.y;
                }
                if (EPI == 1) { v.x = fmaxf(v.x, 0.f); v.y = fmaxf(v.y, 0.f); }
                if (EPI >= 2) {
                    float2 rr = *(const float2*)(Rrow + col);
                    v.x += rr.x; v.y += rr.y;
                }
                *(float2*)&Crow[col] = v;
            }
        }
    }
}

// ---------------- tensor-core flash attention, 64q x 64k, cp.async KV --------
// grid: (QLEN/64, BSZ, NH), 256 threads (8 warps). Double-buffered K/V via
// cp.async. qb reversed so longest CTAs launch first. 3 barriers per tile.
#define AT_KS 68
#define AT_VS 72
#define AT_SS 68
#define AT_QS 68
#define AT_KS_OFF 0                              /* Ks[2][64*68] */
#define AT_VS_OFF (2 * 64 * AT_KS)               /* Vs[2][64*72] */
#define AT_SS_OFF (AT_VS_OFF + 2 * 64 * AT_VS)   /* Ss[64*68]    */
#define AT_ML_OFF (AT_SS_OFF + 64 * AT_SS)
#define AT_SMEM ((AT_ML_OFF + 192) * 4)          /* 89856 bytes */

__global__ __launch_bounds__(256)
void attn_tc_kernel(const float* __restrict__ Q, const float* __restrict__ KV,
                    float* __restrict__ Vout) {
    extern __shared__ __align__(16) float smf[];
    float* Ks0 = smf + AT_KS_OFF;
    float* Ks1 = smf + AT_KS_OFF + 64 * AT_KS;
    float* Vs0 = smf + AT_VS_OFF;
    float* Vs1 = smf + AT_VS_OFF + 64 * AT_VS;
    float* Ss  = smf + AT_SS_OFF;
    float* m_s = smf + AT_ML_OFF;
    float* l_s = m_s + 64;
    float* al_s = m_s + 128;

    // reversed qb: heaviest (largest nTiles) CTAs start first
    const int qb = (QLEN / 64 - 1) - blockIdx.x;
    const int b = blockIdx.y, hh = blockIdx.z;
    const int t = threadIdx.x, lane = t & 31, warp = t >> 5;
    const int lr = lane >> 2, lc = lane & 3;

    const int kb2 = (warp & 1) * 32;     // QK: kj half
    const int nq0 = (warp >> 1) * 16;    // QK: q columns
    const int mq0 = (warp & 3) * 16;     // PV: q rows
    const int nd0 = (warp >> 2) * 32;    // PV: d cols
    const int kjA = t >> 4;              // KV staging rows kjA + 16s
    const int d4A = (t & 15) * 4;

    const int nTiles = 17 + qb;
    const int lastTile = nTiles - 1;

    // issue cp.async for KV tile 0 into buffer 0 (overlaps with Q staging)
#pragma unroll
    for (int s = 0; s < 4; s++) {
        const float* base = &KV[((size_t)(kjA + 16 * s) * BSZ + b) * (2 * DMODEL)
                                + hh * DHEAD + d4A];
        cp16(&Ks0[(kjA + 16 * s) * AT_KS + d4A], base);
        cp16(&Vs0[(kjA + 16 * s) * AT_VS + d4A], base + DMODEL);
    }
    CP_COMMIT();

    // Q (tf32-rounded) into Ss overlay (stride 68, float4-aligned)
    float* Qs = Ss;
    for (int idx = t; idx < 64 * 16; idx += 256) {
        int qi = idx >> 4, d4 = (idx & 15) * 4;
        float4 v = *(const float4*)&Q[((size_t)((qb * 64 + qi) * BSZ + b)) * DMODEL
                                      + hh * DHEAD + d4];
        *(float4*)&Qs[qi * AT_QS + d4] = tf4(v);
    }
    if (t < 64) { m_s[t] = -INFINITY; l_s[t] = 0.0f; }
    __syncthreads();

    // persistent Q fragments
    uint32_t qf[2][8][2];
#pragma unroll
    for (int nt = 0; nt < 2; nt++)
#pragma unroll
        for (int c = 0; c < 8; c++) {
            int qcol = nq0 + nt * 8 + lr;
            qf[nt][c][0] = __float_as_uint(Qs[qcol * AT_QS + c * 8 + lc]);
            qf[nt][c][1] = __float_as_uint(Qs[qcol * AT_QS + c * 8 + lc + 4]);
        }

    float oacc[4][4];
#pragma unroll
    for (int i = 0; i < 4; i++)
#pragma unroll
        for (int j = 0; j < 4; j++) oacc[i][j] = 0.0f;

    int buf = 0;
    for (int tile = 0; tile < nTiles; tile++) {
        const int j0 = tile * 64;
        const float* Ks = buf ? Ks1 : Ks0;
        const float* Vs = buf ? Vs1 : Vs0;
        float* KsN = buf ? Ks0 : Ks1;
        float* VsN = buf ? Vs0 : Vs1;

        CP_WAIT0();
        __syncthreads();   // (1) KV[buf] ready; prev PV readers of buf^1 done;
                           //     on tile 0 also: qf extraction done before Ss reuse

        // issue cp.async for next tile into the other buffer
        if (tile + 1 < nTiles) {
#pragma unroll
            for (int s = 0; s < 4; s++) {
                const float* base = &KV[((size_t)(j0 + 64 + kjA + 16 * s) * BSZ + b)
                                        * (2 * DMODEL) + hh * DHEAD + d4A];
                cp16(&KsN[(kjA + 16 * s) * AT_KS + d4A], base);
                cp16(&VsN[(kjA + 16 * s) * AT_VS + d4A], base + DMODEL);
            }
            CP_COMMIT();
        }

        // S^T = K @ Q^T : 2 kj-tiles x 2 q-tiles per warp
        float sacc[2][2][4];
#pragma unroll
        for (int i = 0; i < 2; i++)
#pragma unroll
            for (int j = 0; j < 2; j++)
#pragma unroll
                for (int r = 0; r < 4; r++) sacc[i][j][r] = 0.0f;
#pragma unroll
        for (int mt2 = 0; mt2 < 2; mt2++) {
#pragma unroll
            for (int c = 0; c < 8; c++) {
                uint32_t af[4];
                int kr0 = (kb2 + mt2 * 16 + lr) * AT_KS;
                af[0] = __float_as_uint(Ks[kr0 + c * 8 + lc]);
                af[1] = __float_as_uint(Ks[kr0 + 8 * AT_KS + c * 8 + lc]);
                af[2] = __float_as_uint(Ks[kr0 + c * 8 + lc + 4]);
                af[3] = __float_as_uint(Ks[kr0 + 8 * AT_KS + c * 8 + lc + 4]);
                mma_tf32(sacc[mt2][0], af, qf[0][c]);
                mma_tf32(sacc[mt2][1], af, qf[1][c]);
            }
        }
        const bool maskTile = (tile == lastTile);
#pragma unroll
        for (int mt2 = 0; mt2 < 2; mt2++)
#pragma unroll
            for (int nt = 0; nt < 2; nt++)
#pragma unroll
                for (int i = 0; i < 4; i++) {
                    int kjl = kb2 + mt2 * 16 + lr + ((i >> 1) ? 8 : 0);
                    int ql  = nq0 + nt * 8 + 2 * lc + (i & 1);
                    float v = sacc[mt2][nt][i] * 0.125f;
                    if (maskTile && (j0 + kjl > MLEN + qb * 64 + ql)) v = -INFINITY;
                    Ss[ql * AT_SS + kjl] = v;
                }
        __syncthreads();   // (2) scores visible to softmax

        // online softmax over 64 keys (fast exp; raw fp32 P, mma truncates)
        {
            int srow = t >> 2, sq = t & 3;
            float sv[16];
            float mx = -INFINITY;
#pragma unroll
            for (int j = 0; j < 16; j++) {
                sv[j] = Ss[srow * AT_SS + 4 * j + sq];
                mx = fmaxf(mx, sv[j]);
            }
            mx = fmaxf(mx, __shfl_xor_sync(0xffffffffu, mx, 1));
            mx = fmaxf(mx, __shfl_xor_sync(0xffffffffu, mx, 2));
            float mOld = m_s[srow];
            float mNew = fmaxf(mOld, mx);
            float al   = __expf(mOld - mNew);
            float sum = 0.0f;
#pragma unroll
            for (int j = 0; j < 16; j++) {
                float p = __expf(sv[j] - mNew);
                Ss[srow * AT_SS + 4 * j + sq] = p;
                sum += p;
            }
            sum += __shfl_xor_sync(0xffffffffu, sum, 1);
            sum += __shfl_xor_sync(0xffffffffu, sum, 2);
            if (sq == 0) { m_s[srow] = mNew; l_s[srow] = l_s[srow] * al + sum; al_s[srow] = al; }
        }
        __syncthreads();   // (3) probs + al visible to PV

        // O += P @ V : 8 kj-chunks
        float a0 = al_s[mq0 + lr], a1 = al_s[mq0 + 8 + lr];
#pragma unroll
        for (int nt = 0; nt < 4; nt++) {
            oacc[nt][0] *= a0; oacc[nt][1] *= a0;
            oacc[nt][2] *= a1; oacc[nt][3] *= a1;
        }
#pragma unroll
        for (int c = 0; c < 8; c++) {
            uint32_t af[4];
            int pr0 = (mq0 + lr) * AT_SS;
            af[0] = __float_as_uint(Ss[pr0 + c * 8 + lc]);
            af[1] = __float_as_uint(Ss[pr0 + 8 * AT_SS + c * 8 + lc]);
            af[2] = __float_as_uint(Ss[pr0 + c * 8 + lc + 4]);
            af[3] = __float_as_uint(Ss[pr0 + 8 * AT_SS + c * 8 + lc + 4]);
#pragma unroll
            for (int nt = 0; nt < 4; nt++) {
                uint32_t bfv[2];
                bfv[0] = __float_as_uint(Vs[(c * 8 + lc) * AT_VS + nd0 + nt * 8 + lr]);
                bfv[1] = __float_as_uint(Vs[(c * 8 + lc + 4) * AT_VS + nd0 + nt * 8 + lr]);
                mma_tf32(oacc[nt], af, bfv);
            }
        }
        buf ^= 1;
    }

    // final normalize + store
#pragma unroll
    for (int half = 0; half < 2; half++) {
        int q = mq0 + lr + half * 8;
        float invl = 1.0f / l_s[q];
        float* orow = &Vout[((size_t)((qb * 64 + q) * BSZ + b)) * DMODEL + hh * DHEAD];
#pragma unroll
        for (int nt = 0; nt < 4; nt++) {
            float2 v = make_float2(oacc[nt][half * 2] * invl, oacc[nt][half * 2 + 1] * invl);
            *(float2*)&orow[nd0 + nt * 8 + 2 * lc] = v;
        }
    }
}

// ---------------- layernorm ---------------------------------------------------
__global__ __launch_bounds__(128)
void ln_kernel(const float* __restrict__ x, const float* __restrict__ g,
               const float* __restrict__ bparm, float* __restrict__ out) {
    const int row = blockIdx.x;
    const int t = threadIdx.x;
    float4 v = ((const float4*)(x + (size_t)row * DMODEL))[t];
    float s  = v.x + v.y + v.z + v.w;
    float s2 = fmaf(v.x, v.x, fmaf(v.y, v.y, fmaf(v.z, v.z, v.w * v.w)));
#pragma unroll
    for (int o = 16; o > 0; o >>= 1) {
        s  += __shfl_down_sync(0xffffffffu, s, o);
        s2 += __shfl_down_sync(0xffffffffu, s2, o);
    }
    __shared__ float ss[4], ss2[4];
    int w = t >> 5;
    if ((t & 31) == 0) { ss[w] = s; ss2[w] = s2; }
    __syncthreads();
    float tot  = ss[0] + ss[1] + ss[2] + ss[3];
    float tot2 = ss2[0] + ss2[1] + ss2[2] + ss2[3];
    float mu  = tot * (1.0f / DMODEL);
    float var = tot2 * (1.0f / DMODEL) - mu * mu;
    float rs  = rsqrtf(var + 1e-5f);
    float4 gg = ((const float4*)g)[t];
    float4 bb = ((const float4*)bparm)[t];
    float4 o;
    o.x = (v.x - mu) * rs * gg.x + bb.x;
    o.y = (v.y - mu) * rs * gg.y + bb.y;
    o.z = (v.z - mu) * rs * gg.z + bb.z;
    o.w = (v.w - mu) * rs * gg.w + bb.w;
    ((float4*)(out + (size_t)row * DMODEL))[t] = o;
}

// ---------------- launch ------------------------------------------------------
extern "C" void kernel_launch(void* const* d_in, const int* in_sizes, int n_in,
                              void* d_out, int out_size) {
    const int*   inp  = (const int*)d_in[0];
    const float* emb  = (const float*)d_in[1];
    const float* mems = (const float*)d_in[2];
    const float* Wq   = (const float*)d_in[3];
    const float* Wkv  = (const float*)d_in[4];
    const float* Wo   = (const float*)d_in[5];
    const float* ln1g = (const float*)d_in[6];
    const float* ln1b = (const float*)d_in[7];
    const float* W1   = (const float*)d_in[8];
    const float* b1   = (const float*)d_in[9];
    const float* W2   = (const float*)d_in[10];
    const float* b2   = (const float*)d_in[11];
    const float* ln2g = (const float*)d_in[12];
    const float* ln2b = (const float*)d_in[13];
    float* out = (float*)d_out;

    float *h, *q, *kv, *vec, *ff, *tmp;
    cudaGetSymbolAddress((void**)&h,   g_h);
    cudaGetSymbolAddress((void**)&q,   g_q);
    cudaGetSymbolAddress((void**)&kv,  g_kv);
    cudaGetSymbolAddress((void**)&vec, g_vec);
    cudaGetSymbolAddress((void**)&ff,  g_ff);
    cudaGetSymbolAddress((void**)&tmp, g_tmp);

    cudaFuncSetAttribute(gemm_tf32_kernel<0, 0>, cudaFuncAttributeMaxDynamicSharedMemorySize, G_SMEM);
    cudaFuncSetAttribute(gemm_tf32_kernel<0, 1>, cudaFuncAttributeMaxDynamicSharedMemorySize, G_SMEM);
    cudaFuncSetAttribute(gemm_tf32_kernel<1, 0>, cudaFuncAttributeMaxDynamicSharedMemorySize, G_SMEM);
    cudaFuncSetAttribute(gemm_tf32_kernel<2, 0>, cudaFuncAttributeMaxDynamicSharedMemorySize, G_SMEM);
    cudaFuncSetAttribute(gemm_tf32_kernel<3, 0>, cudaFuncAttributeMaxDynamicSharedMemorySize, G_SMEM);
    cudaFuncSetAttribute(attn_tc_kernel, cudaFuncAttributeMaxDynamicSharedMemorySize, AT_SMEM);

    embed_kernel<<<(MROWS * DMODEL + 255) / 256, 256>>>(inp, emb, h);

    for (int l = 0; l < NLAYER; l++) {
        const float* mems_l = mems + (size_t)l * MLEN * BSZ * DMODEL;

        gemm_tf32_kernel<0, 0><<<dim3(DMODEL / 128, MROWS / 128), 256, G_SMEM>>>(
            h, nullptr, 0, Wq + (size_t)l * DMODEL * DMODEL, q,
            MROWS, DMODEL, DMODEL, nullptr, nullptr);

        // Wkv GEMM with fused concat: rows < MLEN*BSZ from mems[l], rest from h
        gemm_tf32_kernel<0, 1><<<dim3(2 * DMODEL / 128, CROWS / 128), 256, G_SMEM>>>(
            mems_l, h, MLEN * BSZ, Wkv + (size_t)l * DMODEL * 2 * DMODEL, kv,
            CROWS, 2 * DMODEL, DMODEL, nullptr, nullptr);

        attn_tc_kernel<<<dim3(QLEN / 64, BSZ, NH), 256, AT_SMEM>>>(q, kv, vec);

        gemm_tf32_kernel<2, 0><<<dim3(DMODEL / 128, MROWS / 128), 256, G_SMEM>>>(
            vec, nullptr, 0, Wo + (size_t)l * DMODEL * DMODEL, tmp,
            MROWS, DMODEL, DMODEL, nullptr, h);

        ln_kernel<<<MROWS, 128>>>(tmp, ln1g + l * DMODEL, ln1b + l * DMODEL, h);

        gemm_tf32_kernel<1, 0><<<dim3(DFF / 128, MROWS / 128), 256, G_SMEM>>>(
            h, nullptr, 0, W1 + (size_t)l * DMODEL * DFF, ff,
            MROWS, DFF, DMODEL, b1 + l * DFF, nullptr);

        gemm_tf32_kernel<3, 0><<<dim3(DMODEL / 128, MROWS / 128), 256, G_SMEM>>>(
            ff, nullptr, 0, W2 + (size_t)l * DFF * DMODEL, tmp,
            MROWS, DMODEL, DFF, b2 + l * DMODEL, h);

        ln_kernel<<<MROWS, 128>>>(tmp, ln2g + l * DMODEL, ln2b + l * DMODEL,
                                  (l == NLAYER - 1) ? out : h);
    }
}